// round 1
// baseline (speedup 1.0000x reference)
#include <cuda_runtime.h>
#include <cstdint>
#include <math.h>

// ---------------- problem constants ----------------
constexpr int BB = 64, LQ = 20, LD = 512, DIM = 300, NB = 11, WIN = 5;
constexpr int EQ = 5, ED = 10, DESC = 20, KC = 10;
constexpr int CH = 128;
constexpr int NPAIR = 16;

__constant__ float c_mu[NB]  = {1.0f, 0.9f, 0.7f, 0.5f, 0.3f, 0.1f, -0.1f, -0.3f, -0.5f, -0.7f, -0.9f};
// -0.5 / sigma^2
__constant__ float c_nis[NB] = {-500000.0f, -50.0f, -50.0f, -50.0f, -50.0f, -50.0f, -50.0f, -50.0f, -50.0f, -50.0f, -50.0f};
__constant__ int   c_Lqs[NPAIR] = {20,20,20,19,18,19,19,18,18,5,5,5,20,19,18,5};

// ---------------- scratch layout ----------------
constexpr size_t OFF_QW   = 0;                                   // B*LQ*300
constexpr size_t OFF_DW   = OFF_QW   + (size_t)BB*LQ*DIM;        // B*LD*300
constexpr size_t OFF_QBOW = OFF_DW   + (size_t)BB*LD*DIM;        // B*128
constexpr size_t OFF_DBOW = OFF_QBOW + (size_t)BB*CH;
constexpr size_t OFF_QU   = OFF_DBOW + (size_t)BB*CH;            // B*20*128
constexpr size_t OFF_QB   = OFF_QU   + (size_t)BB*20*CH;         // B*19*128
constexpr size_t OFF_QT   = OFF_QB   + (size_t)BB*19*CH;         // B*18*128
constexpr size_t OFF_DU   = OFF_QT   + (size_t)BB*18*CH;         // B*512*128
constexpr size_t OFF_DB   = OFF_DU   + (size_t)BB*512*CH;        // B*511*128
constexpr size_t OFF_DT   = OFF_DB   + (size_t)BB*511*CH;        // B*510*128
constexpr size_t OFF_QS   = OFF_DT   + (size_t)BB*510*CH;        // B*5*128
constexpr size_t OFF_DS   = OFF_QS   + (size_t)BB*EQ*CH;         // B*10*128
constexpr size_t OFF_PART = OFF_DS   + (size_t)BB*ED*CH;         // 16*B*20*11
constexpr size_t SCRATCH_TOTAL = OFF_PART + (size_t)NPAIR*BB*20*NB;

__device__ float g_scratch[SCRATCH_TOTAL];

// ---------------- gather: out[r,:] = emb[tok[r],:]  (300 floats = 75 float4) ----------------
__global__ void gather_kernel(const float* __restrict__ emb, const int* __restrict__ tok,
                              float* __restrict__ out, int nrows) {
    int idx = blockIdx.x * blockDim.x + threadIdx.x;
    int total = nrows * 75;
    if (idx >= total) return;
    int r = idx / 75, c = idx - r * 75;
    reinterpret_cast<float4*>(out)[idx] =
        reinterpret_cast<const float4*>(emb)[(size_t)tok[r] * 75 + c];
}

// ---------------- bow: out[b,o] = sum_d (sum_l X[b,l,d]) * W[o,d] + L*bias[o] ----------------
__global__ void bow_kernel(const float* __restrict__ X, int L,
                           const float* __restrict__ W, const float* __restrict__ bias,
                           float* __restrict__ out) {
    int b = blockIdx.x, o = threadIdx.x;
    __shared__ float ssum[DIM];
    for (int d = o; d < DIM; d += CH) {
        float s = 0.f;
        const float* xp = X + (size_t)b * L * DIM + d;
        for (int l = 0; l < L; l++) s += xp[(size_t)l * DIM];
        ssum[d] = s;
    }
    __syncthreads();
    float acc = 0.f;
    const float* wr = W + (size_t)o * DIM;
    #pragma unroll 4
    for (int d = 0; d < DIM; d++) acc += ssum[d] * wr[d];
    out[b * CH + o] = acc + (float)L * bias[o];
}

// ---------------- word conv (kernel size K) + relu + per-position L2 norm ----------------
template <int K>
__global__ void __launch_bounds__(128) wordconv_kernel(
        const float* __restrict__ X, int L, int Lout,
        const float* __restrict__ W, const float* __restrict__ bias,
        float* __restrict__ out) {
    constexpr int DC = 60 / K;       // K*DC == 60, 300 % DC == 0 for K in {1,2,3,5}
    constexpr int LT = 16;
    constexpr int WST = 61;          // padded stride, conflict-free
    __shared__ float Ws[CH * WST];
    __shared__ float Xs[(LT + K - 1) * DC];
    __shared__ float outS[LT][CH + 4];

    int n = blockIdx.y;
    int l0 = blockIdx.x * LT;
    int o = threadIdx.x;

    float acc[LT];
    #pragma unroll
    for (int p = 0; p < LT; p++) acc[p] = 0.f;

    for (int d0 = 0; d0 < DIM; d0 += DC) {
        // weight tile: Ws[oc][w*DC+j] = W[oc, w, d0+j]
        for (int i = o; i < CH * (K * DC); i += CH) {
            int oc = i / (K * DC), kk = i - oc * (K * DC);
            int w = kk / DC, j = kk - w * DC;
            Ws[oc * WST + kk] = W[(size_t)oc * K * DIM + (size_t)w * DIM + d0 + j];
        }
        // input tile
        for (int i = o; i < (LT + K - 1) * DC; i += CH) {
            int r = i / DC, j = i - r * DC;
            int lg = l0 + r;
            Xs[i] = (lg < L) ? X[((size_t)n * L + lg) * DIM + d0 + j] : 0.f;
        }
        __syncthreads();
        for (int j = 0; j < DC; j++) {
            float xr[LT + K - 1];
            #pragma unroll
            for (int r = 0; r < LT + K - 1; r++) xr[r] = Xs[r * DC + j];
            #pragma unroll
            for (int w = 0; w < K; w++) {
                float wv = Ws[o * WST + w * DC + j];
                #pragma unroll
                for (int p = 0; p < LT; p++) acc[p] += wv * xr[p + w];
            }
        }
        __syncthreads();
    }
    float bo = bias[o];
    #pragma unroll
    for (int p = 0; p < LT; p++) outS[p][o] = fmaxf(acc[p] + bo, 0.f);
    __syncthreads();

    int warp = o >> 5, lane = o & 31;
    int valid = Lout - l0; if (valid > LT) valid = LT;
    for (int p = warp; p < valid; p += 4) {
        float v0 = outS[p][lane], v1 = outS[p][lane + 32];
        float v2 = outS[p][lane + 64], v3 = outS[p][lane + 96];
        float ss = v0 * v0 + v1 * v1 + v2 * v2 + v3 * v3;
        #pragma unroll
        for (int off = 16; off > 0; off >>= 1) ss += __shfl_xor_sync(0xffffffffu, ss, off);
        float inv = 1.f / fmaxf(sqrtf(ss), 1e-10f);
        float* op = out + ((size_t)n * Lout + l0 + p) * CH;
        op[lane] = v0 * inv; op[lane + 32] = v1 * inv;
        op[lane + 64] = v2 * inv; op[lane + 96] = v3 * inv;
    }
}

// ---------------- entity branch: desc conv(max) + carrier attention + ent emb, L2 norm ----------------
__global__ void __launch_bounds__(128) entity_kernel(
        const int* __restrict__ ids_e, const int* __restrict__ ids_desc,
        const int* __restrict__ ids_car, const float* __restrict__ bow,
        const float* __restrict__ wrd_emb, const float* __restrict__ ent_emb,
        const float* __restrict__ car_emb,
        const float* __restrict__ W, const float* __restrict__ bias,
        int n_ent, float* __restrict__ out) {
    constexpr int K = WIN, DC = 12, LT = 16, WST = 61;  // K*DC = 60
    __shared__ float Ws[CH * WST];
    __shared__ float Xs[DESC * DC];
    __shared__ int toks[DESC];
    __shared__ int crows[KC];
    __shared__ float bv[CH];
    __shared__ float logits[KC];
    __shared__ float att[KC];
    __shared__ float red[4];

    int e = blockIdx.x, b = blockIdx.y;
    int o = threadIdx.x;
    int warp = o >> 5, lane = o & 31;

    if (o < DESC) toks[o] = ids_desc[(size_t)b * n_ent * DESC + e * DESC + o];
    if (o < KC)   crows[o] = ids_car[(size_t)b * n_ent * KC + e * KC + o];
    bv[o] = bow[b * CH + o];
    __syncthreads();

    float acc[LT];
    #pragma unroll
    for (int p = 0; p < LT; p++) acc[p] = 0.f;

    for (int d0 = 0; d0 < DIM; d0 += DC) {
        for (int i = o; i < CH * (K * DC); i += CH) {
            int oc = i / (K * DC), kk = i - oc * (K * DC);
            int w = kk / DC, j = kk - w * DC;
            Ws[oc * WST + kk] = W[(size_t)oc * K * DIM + (size_t)w * DIM + d0 + j];
        }
        for (int i = o; i < DESC * DC; i += CH) {
            int r = i / DC, j = i - r * DC;
            Xs[i] = wrd_emb[(size_t)toks[r] * DIM + d0 + j];
        }
        __syncthreads();
        for (int j = 0; j < DC; j++) {
            float xr[DESC];
            #pragma unroll
            for (int r = 0; r < DESC; r++) xr[r] = Xs[r * DC + j];
            #pragma unroll
            for (int w = 0; w < K; w++) {
                float wv = Ws[o * WST + w * DC + j];
                #pragma unroll
                for (int p = 0; p < LT; p++) acc[p] += wv * xr[p + w];
            }
        }
        __syncthreads();
    }
    float bo = bias[o];
    float econv = 0.f;
    #pragma unroll
    for (int p = 0; p < LT; p++) econv = fmaxf(econv, fmaxf(acc[p] + bo, 0.f));

    // attention logits
    if (o < KC) {
        const float* cr = car_emb + (size_t)crows[o] * CH;
        float s = 0.f;
        #pragma unroll 4
        for (int c = 0; c < CH; c++) s += bv[c] * cr[c];
        logits[o] = s;
    }
    __syncthreads();
    if (o == 0) {
        float mx = -1e30f;
        #pragma unroll
        for (int k = 0; k < KC; k++) mx = fmaxf(mx, logits[k]);
        float ssum = 0.f;
        #pragma unroll
        for (int k = 0; k < KC; k++) { float ev = __expf(logits[k] - mx); att[k] = ev; ssum += ev; }
        float inv = 1.f / ssum;
        #pragma unroll
        for (int k = 0; k < KC; k++) att[k] *= inv;
    }
    __syncthreads();
    float ew = 0.f;
    #pragma unroll
    for (int k = 0; k < KC; k++) ew += att[k] * car_emb[(size_t)crows[k] * CH + o];

    float v = ent_emb[(size_t)ids_e[b * n_ent + e] * CH + o] + econv + ew;

    float ss = v * v;
    #pragma unroll
    for (int off = 16; off > 0; off >>= 1) ss += __shfl_xor_sync(0xffffffffu, ss, off);
    if (lane == 0) red[warp] = ss;
    __syncthreads();
    float tot = red[0] + red[1] + red[2] + red[3];
    float inv = 1.f / fmaxf(sqrtf(tot), 1e-10f);
    out[((size_t)b * n_ent + e) * CH + o] = v * inv;
}

// ---------------- kernel pooling: one block per (b, lq) ----------------
__global__ void __launch_bounds__(256) pool_kernel(
        const float* __restrict__ Q, int Lq,
        const float* __restrict__ Dm, int Ld,
        const float* __restrict__ mq, int mq_stride,
        const float* __restrict__ md, int md_stride,
        int pair, float* __restrict__ part) {
    int lq = blockIdx.x, b = blockIdx.y;
    int t = threadIdx.x;
    __shared__ float4 qv[32];
    __shared__ float wred[8][NB];
    if (t < 32)
        qv[t] = reinterpret_cast<const float4*>(Q + ((size_t)b * Lq + lq) * CH)[t];
    __syncthreads();

    float acc[NB];
    #pragma unroll
    for (int k = 0; k < NB; k++) acc[k] = 0.f;

    for (int ld = t; ld < Ld; ld += 256) {
        const float4* dr = reinterpret_cast<const float4*>(Dm + ((size_t)b * Ld + ld) * CH);
        float s = 0.f;
        #pragma unroll
        for (int i = 0; i < 32; i++) {
            float4 dv = dr[i]; float4 q4 = qv[i];
            s += dv.x * q4.x + dv.y * q4.y + dv.z * q4.z + dv.w * q4.w;
        }
        float m = md[(size_t)b * md_stride + ld];
        #pragma unroll
        for (int k = 0; k < NB; k++) {
            float dd = s - c_mu[k];
            acc[k] += m * __expf(dd * dd * c_nis[k]);
        }
    }
    int warp = t >> 5, lane = t & 31;
    #pragma unroll
    for (int k = 0; k < NB; k++) {
        float v = acc[k];
        #pragma unroll
        for (int off = 16; off > 0; off >>= 1) v += __shfl_xor_sync(0xffffffffu, v, off);
        if (lane == 0) wred[warp][k] = v;
    }
    __syncthreads();
    if (t < NB) {
        float s = 0.f;
        #pragma unroll
        for (int w = 0; w < 8; w++) s += wred[w][t];
        float lp = __logf(fmaxf(s, 1e-10f)) * 0.01f * mq[(size_t)b * mq_stride + lq];
        part[(size_t)pair * BB * 20 * NB + ((size_t)b * 20 + lq) * NB + t] = lp;
    }
}

// ---------------- final: sum partials per feature, dot with dense_f_W, tanh ----------------
__global__ void __launch_bounds__(192) final_kernel(
        const float* __restrict__ part, const float* __restrict__ dW,
        const float* __restrict__ dB, float* __restrict__ out) {
    int b = blockIdx.x, t = threadIdx.x;
    float val = 0.f;
    if (t < NPAIR * NB) {
        int pair = t / NB;
        int k = t - pair * NB;
        int Lqp = c_Lqs[pair];
        const float* pp = part + (size_t)pair * BB * 20 * NB + (size_t)b * 20 * NB + k;
        float s = 0.f;
        for (int lq = 0; lq < Lqp; lq++) s += pp[lq * NB];
        val = s * dW[t];
    }
    int warp = t >> 5, lane = t & 31;
    #pragma unroll
    for (int off = 16; off > 0; off >>= 1) val += __shfl_xor_sync(0xffffffffu, val, off);
    __shared__ float r6[6];
    if (lane == 0) r6[warp] = val;
    __syncthreads();
    if (t == 0) {
        float tot = r6[0] + r6[1] + r6[2] + r6[3] + r6[4] + r6[5];
        out[b] = tanhf(tot + dB[0]);
    }
}

// ---------------- launcher ----------------
extern "C" void kernel_launch(void* const* d_in, const int* in_sizes, int n_in,
                              void* d_out, int out_size) {
    const int*   qwt = (const int*)d_in[0];
    const float* qwm = (const float*)d_in[1];
    const int*   qei = (const int*)d_in[2];
    const int*   qet = (const int*)d_in[3];
    const int*   qew = (const int*)d_in[4];
    const float* qem = (const float*)d_in[5];
    const int*   dwt = (const int*)d_in[6];
    const float* dwm = (const float*)d_in[7];
    const int*   dei = (const int*)d_in[8];
    const int*   det = (const int*)d_in[9];
    const int*   dew = (const int*)d_in[10];
    const float* dem = (const float*)d_in[11];
    const float* wrd = (const float*)d_in[12];
    const float* ent = (const float*)d_in[13];
    const float* car = (const float*)d_in[14];
    const float* bowW = (const float*)d_in[15];
    const float* bowB = (const float*)d_in[16];
    const float* cuW = (const float*)d_in[17];
    const float* cuB = (const float*)d_in[18];
    const float* cbW = (const float*)d_in[19];
    const float* cbB = (const float*)d_in[20];
    const float* ctW = (const float*)d_in[21];
    const float* ctB = (const float*)d_in[22];
    const float* cdW = (const float*)d_in[23];
    const float* cdB = (const float*)d_in[24];
    const float* dfW = (const float*)d_in[25];
    const float* dfB = (const float*)d_in[26];
    float* out = (float*)d_out;

    float* S = nullptr;
    cudaGetSymbolAddress((void**)&S, g_scratch);
    float* qw    = S + OFF_QW;
    float* dw    = S + OFF_DW;
    float* qbow  = S + OFF_QBOW;
    float* dbow  = S + OFF_DBOW;
    float* qu    = S + OFF_QU;
    float* qb    = S + OFF_QB;
    float* qt    = S + OFF_QT;
    float* du    = S + OFF_DU;
    float* db    = S + OFF_DB;
    float* dt    = S + OFF_DT;
    float* qs    = S + OFF_QS;
    float* ds    = S + OFF_DS;
    float* partial = S + OFF_PART;

    gather_kernel<<<(BB * LQ * 75 + 255) / 256, 256>>>(wrd, qwt, qw, BB * LQ);
    gather_kernel<<<(BB * LD * 75 + 255) / 256, 256>>>(wrd, dwt, dw, BB * LD);

    bow_kernel<<<BB, 128>>>(qw, LQ, bowW, bowB, qbow);
    bow_kernel<<<BB, 128>>>(dw, LD, bowW, bowB, dbow);

    entity_kernel<<<dim3(EQ, BB), 128>>>(qei, qet, qew, qbow, wrd, ent, car, cdW, cdB, EQ, qs);
    entity_kernel<<<dim3(ED, BB), 128>>>(dei, det, dew, dbow, wrd, ent, car, cdW, cdB, ED, ds);

    wordconv_kernel<1><<<dim3(2, BB), 128>>>(qw, LQ, 20, cuW, cuB, qu);
    wordconv_kernel<2><<<dim3(2, BB), 128>>>(qw, LQ, 19, cbW, cbB, qb);
    wordconv_kernel<3><<<dim3(2, BB), 128>>>(qw, LQ, 18, ctW, ctB, qt);
    wordconv_kernel<1><<<dim3(32, BB), 128>>>(dw, LD, 512, cuW, cuB, du);
    wordconv_kernel<2><<<dim3(32, BB), 128>>>(dw, LD, 511, cbW, cbB, db);
    wordconv_kernel<3><<<dim3(32, BB), 128>>>(dw, LD, 510, ctW, ctB, dt);

    struct PairCfg { const float* Q; int Lq; const float* mq; int mqs;
                     const float* D; int Ld; const float* md; int mds; };
    PairCfg pc[NPAIR] = {
        { qu, 20, qwm, 20,  du, 512, dwm, 512 },
        { qu, 20, qwm, 20,  dt, 510, dwm, 512 },
        { qu, 20, qwm, 20,  db, 511, dwm, 512 },
        { qb, 19, qwm, 20,  du, 512, dwm, 512 },
        { qt, 18, qwm, 20,  du, 512, dwm, 512 },
        { qb, 19, qwm, 20,  db, 511, dwm, 512 },
        { qb, 19, qwm, 20,  dt, 510, dwm, 512 },
        { qt, 18, qwm, 20,  db, 511, dwm, 512 },
        { qt, 18, qwm, 20,  dt, 510, dwm, 512 },
        { qs,  5, qem,  5,  du, 512, dwm, 512 },
        { qs,  5, qem,  5,  db, 511, dwm, 512 },
        { qs,  5, qem,  5,  dt, 510, dwm, 512 },
        { qu, 20, qwm, 20,  ds,  10, dem,  10 },
        { qb, 19, qwm, 20,  ds,  10, dem,  10 },
        { qt, 18, qwm, 20,  ds,  10, dem,  10 },
        { qs,  5, qem,  5,  ds,  10, dem,  10 },
    };
    for (int p = 0; p < NPAIR; p++) {
        pool_kernel<<<dim3(pc[p].Lq, BB), 256>>>(
            pc[p].Q, pc[p].Lq, pc[p].D, pc[p].Ld,
            pc[p].mq, pc[p].mqs, pc[p].md, pc[p].mds, p, partial);
    }

    final_kernel<<<BB, 192>>>(partial, dfW, dfB, out);
}

// round 2
// speedup vs baseline: 1.5859x; 1.5859x over previous
#include <cuda_runtime.h>
#include <cstdint>
#include <math.h>

// ---------------- problem constants ----------------
constexpr int BB = 64, LQ = 20, LD = 512, DIM = 300, NB = 11, WIN = 5;
constexpr int EQ = 5, ED = 10, DESC = 20, KC = 10;
constexpr int CH = 128;
constexpr int NPAIR = 16;
constexpr int QR_TOT = 64;     // 62 real q rows (20+19+18+5) padded to 64
constexpr int PSLOTS = 13;     // 4 chunks x 3 big D mats + 1 for ds

__constant__ float c_mu[NB]  = {1.0f, 0.9f, 0.7f, 0.5f, 0.3f, 0.1f, -0.1f, -0.3f, -0.5f, -0.7f, -0.9f};
// -0.5 / sigma^2
__constant__ float c_nis[NB] = {-500000.0f, -50.0f, -50.0f, -50.0f, -50.0f, -50.0f, -50.0f, -50.0f, -50.0f, -50.0f, -50.0f};

// pair -> (q source, d source) per reference pools order
__constant__ int c_pq[NPAIR]  = {0,0,0,1,2,1,1,2,2,3,3,3,0,1,2,3};
__constant__ int c_pd[NPAIR]  = {0,2,1,0,0,1,2,1,2,0,1,2,3,3,3,3};
__constant__ int c_qoff[4]    = {0,20,39,57};
__constant__ int c_qlen[4]    = {20,19,18,5};
__constant__ int c_dslot[4]   = {0,4,8,12};
__constant__ int c_dnch[4]    = {4,4,4,1};

// ---------------- scratch layout ----------------
constexpr size_t OFF_QW   = 0;                                   // B*LQ*300
constexpr size_t OFF_DW   = OFF_QW   + (size_t)BB*LQ*DIM;        // B*LD*300
constexpr size_t OFF_QBOW = OFF_DW   + (size_t)BB*LD*DIM;        // B*128
constexpr size_t OFF_DBOW = OFF_QBOW + (size_t)BB*CH;
constexpr size_t OFF_QU   = OFF_DBOW + (size_t)BB*CH;            // B*20*128
constexpr size_t OFF_QB   = OFF_QU   + (size_t)BB*20*CH;         // B*19*128
constexpr size_t OFF_QT   = OFF_QB   + (size_t)BB*19*CH;         // B*18*128
constexpr size_t OFF_DU   = OFF_QT   + (size_t)BB*18*CH;         // B*512*128
constexpr size_t OFF_DB   = OFF_DU   + (size_t)BB*512*CH;        // B*511*128
constexpr size_t OFF_DT   = OFF_DB   + (size_t)BB*511*CH;        // B*510*128
constexpr size_t OFF_QS   = OFF_DT   + (size_t)BB*510*CH;        // B*5*128
constexpr size_t OFF_DS   = OFF_QS   + (size_t)BB*EQ*CH;         // B*10*128
constexpr size_t OFF_CS1  = OFF_DS   + (size_t)BB*ED*CH;         // B*300     (q colsum)
constexpr size_t OFF_CS8  = OFF_CS1  + (size_t)BB*DIM;           // B*8*300   (d colsum)
constexpr size_t OFF_PART = OFF_CS8  + (size_t)BB*8*DIM;         // 13*B*64*11
constexpr size_t SCRATCH_TOTAL = OFF_PART + (size_t)PSLOTS*BB*QR_TOT*NB;

__device__ float g_scratch[SCRATCH_TOTAL];

// ---------------- gather: out[r,:] = emb[tok[r],:]  (300 floats = 75 float4) ----------------
__global__ void gather_kernel(const float* __restrict__ emb, const int* __restrict__ tok,
                              float* __restrict__ out, int nrows) {
    int idx = blockIdx.x * blockDim.x + threadIdx.x;
    int total = nrows * 75;
    if (idx >= total) return;
    int r = idx / 75, c = idx - r * 75;
    reinterpret_cast<float4*>(out)[idx] =
        reinterpret_cast<const float4*>(emb)[(size_t)tok[r] * 75 + c];
}

// ---------------- column-sum partials: out[b,c,d] = sum over rows chunk c ----------------
__global__ void colsum_kernel(const float* __restrict__ X, int L, int rows,
                              float* __restrict__ outp) {
    int c = blockIdx.x, b = blockIdx.y;
    int NC = gridDim.x;
    int t = threadIdx.x;
    int r0 = c * rows;
    for (int d = t; d < DIM; d += blockDim.x) {
        float s = 0.f;
        #pragma unroll 4
        for (int r = 0; r < rows; r++) {
            int row = r0 + r;
            if (row < L) s += X[((size_t)b * L + row) * DIM + d];
        }
        outp[((size_t)b * NC + c) * DIM + d] = s;
    }
}

// ---------------- bow stage2: reduce partials + matvec with bow_W ----------------
__global__ void bow2_kernel(const float* __restrict__ partS, int NC, int L,
                            const float* __restrict__ W, const float* __restrict__ bias,
                            float* __restrict__ out) {
    int b = blockIdx.x, o = threadIdx.x;   // 128 threads
    __shared__ float ssum[DIM];
    for (int d = o; d < DIM; d += CH) {
        float s = 0.f;
        for (int c = 0; c < NC; c++) s += partS[((size_t)b * NC + c) * DIM + d];
        ssum[d] = s;
    }
    __syncthreads();
    float acc = 0.f;
    const float* wr = W + (size_t)o * DIM;
    #pragma unroll 4
    for (int d = 0; d < DIM; d++) acc += ssum[d] * wr[d];
    out[b * CH + o] = acc + (float)L * bias[o];
}

// ---------------- word conv (kernel size K) + relu + per-position L2 norm ----------------
// Register-blocked: 128 threads = 32 channel-groups x 4 position-warps.
// Thread (cg, pg) computes channels {cg, cg+32, cg+64, cg+96} x positions pg*8..pg*8+7.
template <int K>
__global__ void __launch_bounds__(128) wordconv2_kernel(
        const float* __restrict__ X, int L, int Lout,
        const float* __restrict__ W, const float* __restrict__ bias,
        float* __restrict__ out) {
    constexpr int DC = 60 / K;       // dims per tile
    constexpr int KD = K * DC;       // 60
    constexpr int WST = KD + 1;      // 61, conflict-free
    constexpr int LT = 32;
    constexpr int XR = LT + K - 1;
    __shared__ float Ws[CH * WST];
    __shared__ float Xs[XR * DC];

    int n = blockIdx.y;
    int l0 = blockIdx.x * LT;
    int t = threadIdx.x;
    int cg = t & 31, pg = t >> 5;

    float acc[4][8];
    #pragma unroll
    for (int u = 0; u < 4; u++)
        #pragma unroll
        for (int r = 0; r < 8; r++) acc[u][r] = 0.f;

    for (int d0 = 0; d0 < DIM; d0 += DC) {
        __syncthreads();
        for (int i = t; i < CH * KD; i += 128) {
            int ch = i / KD, kk = i - ch * KD;
            int w = kk / DC, j = kk - w * DC;
            Ws[ch * WST + kk] = W[(size_t)ch * K * DIM + (size_t)w * DIM + d0 + j];
        }
        for (int i = t; i < XR * DC; i += 128) {
            int r = i / DC, j = i - r * DC;
            int lg = l0 + r;
            Xs[i] = (lg < L) ? X[((size_t)n * L + lg) * DIM + d0 + j] : 0.f;
        }
        __syncthreads();
        for (int j = 0; j < DC; j++) {
            float xr[8 + K - 1];
            #pragma unroll
            for (int r = 0; r < 8 + K - 1; r++) xr[r] = Xs[(pg * 8 + r) * DC + j];
            #pragma unroll
            for (int u = 0; u < 4; u++) {
                const float* wrow = &Ws[(cg + 32 * u) * WST + j];
                #pragma unroll
                for (int w = 0; w < K; w++) {
                    float wv = wrow[w * DC];
                    #pragma unroll
                    for (int r = 0; r < 8; r++) acc[u][r] += wv * xr[r + w];
                }
            }
        }
    }

    float bvals[4];
    #pragma unroll
    for (int u = 0; u < 4; u++) bvals[u] = bias[cg + 32 * u];

    #pragma unroll
    for (int r = 0; r < 8; r++) {
        int p = pg * 8 + r;
        float v[4];
        float ss = 0.f;
        #pragma unroll
        for (int u = 0; u < 4; u++) {
            v[u] = fmaxf(acc[u][r] + bvals[u], 0.f);
            ss += v[u] * v[u];
        }
        #pragma unroll
        for (int off = 16; off > 0; off >>= 1) ss += __shfl_xor_sync(0xffffffffu, ss, off);
        float inv = 1.f / fmaxf(sqrtf(ss), 1e-10f);
        if (l0 + p < Lout) {
            float* op = out + ((size_t)n * Lout + l0 + p) * CH;
            #pragma unroll
            for (int u = 0; u < 4; u++) op[cg + 32 * u] = v[u] * inv;
        }
    }
}

// ---------------- entity branch: desc conv(max) + carrier attention + ent emb, L2 norm ----------------
__global__ void __launch_bounds__(128) entity_kernel(
        const int* __restrict__ ids_e, const int* __restrict__ ids_desc,
        const int* __restrict__ ids_car, const float* __restrict__ bow,
        const float* __restrict__ wrd_emb, const float* __restrict__ ent_emb,
        const float* __restrict__ car_emb,
        const float* __restrict__ W, const float* __restrict__ bias,
        int n_ent, float* __restrict__ out) {
    constexpr int K = WIN, DC = 12, LT = 16, WST = 61;  // K*DC = 60
    __shared__ float Ws[CH * WST];
    __shared__ float Xs[DESC * DC];
    __shared__ int toks[DESC];
    __shared__ int crows[KC];
    __shared__ float bv[CH];
    __shared__ float logits[KC];
    __shared__ float att[KC];
    __shared__ float red[4];

    int e = blockIdx.x, b = blockIdx.y;
    int o = threadIdx.x;
    int warp = o >> 5, lane = o & 31;

    if (o < DESC) toks[o] = ids_desc[(size_t)b * n_ent * DESC + e * DESC + o];
    if (o < KC)   crows[o] = ids_car[(size_t)b * n_ent * KC + e * KC + o];
    bv[o] = bow[b * CH + o];
    __syncthreads();

    float acc[LT];
    #pragma unroll
    for (int p = 0; p < LT; p++) acc[p] = 0.f;

    for (int d0 = 0; d0 < DIM; d0 += DC) {
        for (int i = o; i < CH * (K * DC); i += CH) {
            int oc = i / (K * DC), kk = i - oc * (K * DC);
            int w = kk / DC, j = kk - w * DC;
            Ws[oc * WST + kk] = W[(size_t)oc * K * DIM + (size_t)w * DIM + d0 + j];
        }
        for (int i = o; i < DESC * DC; i += CH) {
            int r = i / DC, j = i - r * DC;
            Xs[i] = wrd_emb[(size_t)toks[r] * DIM + d0 + j];
        }
        __syncthreads();
        for (int j = 0; j < DC; j++) {
            float xr[DESC];
            #pragma unroll
            for (int r = 0; r < DESC; r++) xr[r] = Xs[r * DC + j];
            #pragma unroll
            for (int w = 0; w < K; w++) {
                float wv = Ws[o * WST + w * DC + j];
                #pragma unroll
                for (int p = 0; p < LT; p++) acc[p] += wv * xr[p + w];
            }
        }
        __syncthreads();
    }
    float bo = bias[o];
    float econv = 0.f;
    #pragma unroll
    for (int p = 0; p < LT; p++) econv = fmaxf(econv, fmaxf(acc[p] + bo, 0.f));

    if (o < KC) {
        const float* cr = car_emb + (size_t)crows[o] * CH;
        float s = 0.f;
        #pragma unroll 4
        for (int c = 0; c < CH; c++) s += bv[c] * cr[c];
        logits[o] = s;
    }
    __syncthreads();
    if (o == 0) {
        float mx = -1e30f;
        #pragma unroll
        for (int k = 0; k < KC; k++) mx = fmaxf(mx, logits[k]);
        float ssum = 0.f;
        #pragma unroll
        for (int k = 0; k < KC; k++) { float ev = __expf(logits[k] - mx); att[k] = ev; ssum += ev; }
        float inv = 1.f / ssum;
        #pragma unroll
        for (int k = 0; k < KC; k++) att[k] *= inv;
    }
    __syncthreads();
    float ew = 0.f;
    #pragma unroll
    for (int k = 0; k < KC; k++) ew += att[k] * car_emb[(size_t)crows[k] * CH + o];

    float v = ent_emb[(size_t)ids_e[b * n_ent + e] * CH + o] + econv + ew;

    float ss = v * v;
    #pragma unroll
    for (int off = 16; off > 0; off >>= 1) ss += __shfl_xor_sync(0xffffffffu, ss, off);
    if (lane == 0) red[warp] = ss;
    __syncthreads();
    float tot = red[0] + red[1] + red[2] + red[3];
    float inv = 1.f / fmaxf(sqrtf(tot), 1e-10f);
    out[((size_t)b * n_ent + e) * CH + o] = v * inv;
}

// ---------------- fused kernel pooling: one D matrix vs ALL 62 q rows ----------------
// Grid (nchunk, B), 256 threads. Thread t: qr = t>>2 (q row), g = t&3 (dim group).
// Each thread holds 32 dims of its q row in registers (float4s g, g+4, ..., g+28).
// D rows staged 8 at a time in smem; dot reduced over g via shfl; lane g
// accumulates RBF kernels {g, g+4, g+8}. Partials written per (slot,b,qr,k).
__global__ void __launch_bounds__(256) pool_fused_kernel(
        const float* __restrict__ Qu, const float* __restrict__ Qb,
        const float* __restrict__ Qt, const float* __restrict__ Qs,
        const float* __restrict__ D, int Ld,
        const float* __restrict__ md, int md_stride,
        int chunkRows, int slotBase, float* __restrict__ part) {
    int chunk = blockIdx.x, b = blockIdx.y;
    int t = threadIdx.x;
    int qr = t >> 2, g = t & 3;

    // load this thread's 32 q dims into registers
    float4 qreg[8];
    const float* qptr = nullptr;
    if (qr < 20)      qptr = Qu + (size_t)(b * 20 + qr) * CH;
    else if (qr < 39) qptr = Qb + (size_t)(b * 19 + (qr - 20)) * CH;
    else if (qr < 57) qptr = Qt + (size_t)(b * 18 + (qr - 39)) * CH;
    else if (qr < 62) qptr = Qs + (size_t)(b * 5 + (qr - 57)) * CH;
    if (qptr) {
        const float4* q4 = reinterpret_cast<const float4*>(qptr);
        #pragma unroll
        for (int i = 0; i < 8; i++) qreg[i] = q4[g + 4 * i];
    } else {
        #pragma unroll
        for (int i = 0; i < 8; i++) qreg[i] = make_float4(0.f, 0.f, 0.f, 0.f);
    }

    float mu0 = c_mu[g],     ni0 = c_nis[g];
    float mu1 = c_mu[g + 4], ni1 = c_nis[g + 4];
    float mu2 = 0.f, ni2 = 0.f;
    bool has2 = (g + 8) < NB;
    if (has2) { mu2 = c_mu[g + 8]; ni2 = c_nis[g + 8]; }

    float acc0 = 0.f, acc1 = 0.f, acc2 = 0.f;

    __shared__ float Ds[8][CH];
    __shared__ float msk[8];

    int ld_begin = chunk * chunkRows;
    for (int ld0 = ld_begin; ld0 < ld_begin + chunkRows; ld0 += 8) {
        __syncthreads();
        {
            int r = t >> 5, c = t & 31;   // 8 rows x 32 float4 cols
            int row = ld0 + r;
            float4 v = make_float4(0.f, 0.f, 0.f, 0.f);
            if (row < Ld)
                v = reinterpret_cast<const float4*>(D + ((size_t)b * Ld + row) * CH)[c];
            reinterpret_cast<float4*>(&Ds[r][0])[c] = v;
            if (t < 8) {
                int rr = ld0 + t;
                msk[t] = (rr < Ld) ? md[(size_t)b * md_stride + rr] : 0.f;
            }
        }
        __syncthreads();
        #pragma unroll
        for (int r = 0; r < 8; r++) {
            const float4* dp = reinterpret_cast<const float4*>(&Ds[r][0]);
            float s = 0.f;
            #pragma unroll
            for (int i = 0; i < 8; i++) {
                float4 d4 = dp[g + 4 * i];
                float4 q4 = qreg[i];
                s += d4.x * q4.x + d4.y * q4.y + d4.z * q4.z + d4.w * q4.w;
            }
            s += __shfl_xor_sync(0xffffffffu, s, 1);
            s += __shfl_xor_sync(0xffffffffu, s, 2);
            float m = msk[r];
            float dd0 = s - mu0; acc0 += m * __expf(dd0 * dd0 * ni0);
            float dd1 = s - mu1; acc1 += m * __expf(dd1 * dd1 * ni1);
            if (has2) { float dd2 = s - mu2; acc2 += m * __expf(dd2 * dd2 * ni2); }
        }
    }

    size_t base = ((size_t)(slotBase + chunk) * BB + b) * (QR_TOT * NB) + (size_t)qr * NB;
    part[base + g]     = acc0;
    part[base + g + 4] = acc1;
    if (has2) part[base + g + 8] = acc2;
}

// ---------------- final: reduce chunk partials, log, mask, dense dot, tanh ----------------
__global__ void __launch_bounds__(256) final_kernel(
        const float* __restrict__ part, const float* __restrict__ qwm,
        const float* __restrict__ qem, const float* __restrict__ dW,
        const float* __restrict__ dB, float* __restrict__ out) {
    int b = blockIdx.x, t = threadIdx.x;
    float local = 0.f;
    for (int p = 0; p < NPAIR; p++) {
        int qsrc = c_pq[p], dmat = c_pd[p];
        int Lqp = c_qlen[qsrc], off = c_qoff[qsrc];
        int slot = c_dslot[dmat], nch = c_dnch[dmat];
        int tot = Lqp * NB;
        for (int idx = t; idx < tot; idx += 256) {
            int lq = idx / NB, k = idx - lq * NB;
            int row = off + lq;
            float s = 0.f;
            for (int c = 0; c < nch; c++)
                s += part[((size_t)(slot + c) * BB + b) * (QR_TOT * NB) + row * NB + k];
            float mq = (qsrc < 3) ? qwm[b * 20 + lq] : qem[b * 5 + lq];
            local += dW[p * NB + k] * (__logf(fmaxf(s, 1e-10f)) * 0.01f * mq);
        }
    }
    #pragma unroll
    for (int off = 16; off > 0; off >>= 1) local += __shfl_xor_sync(0xffffffffu, local, off);
    __shared__ float r8[8];
    if ((t & 31) == 0) r8[t >> 5] = local;
    __syncthreads();
    if (t == 0) {
        float s = 0.f;
        #pragma unroll
        for (int w = 0; w < 8; w++) s += r8[w];
        out[b] = tanhf(s + dB[0]);
    }
}

// ---------------- launcher ----------------
extern "C" void kernel_launch(void* const* d_in, const int* in_sizes, int n_in,
                              void* d_out, int out_size) {
    const int*   qwt = (const int*)d_in[0];
    const float* qwm = (const float*)d_in[1];
    const int*   qei = (const int*)d_in[2];
    const int*   qet = (const int*)d_in[3];
    const int*   qew = (const int*)d_in[4];
    const float* qem = (const float*)d_in[5];
    const int*   dwt = (const int*)d_in[6];
    const float* dwm = (const float*)d_in[7];
    const int*   dei = (const int*)d_in[8];
    const int*   det = (const int*)d_in[9];
    const int*   dew = (const int*)d_in[10];
    const float* dem = (const float*)d_in[11];
    const float* wrd = (const float*)d_in[12];
    const float* ent = (const float*)d_in[13];
    const float* car = (const float*)d_in[14];
    const float* bowW = (const float*)d_in[15];
    const float* bowB = (const float*)d_in[16];
    const float* cuW = (const float*)d_in[17];
    const float* cuB = (const float*)d_in[18];
    const float* cbW = (const float*)d_in[19];
    const float* cbB = (const float*)d_in[20];
    const float* ctW = (const float*)d_in[21];
    const float* ctB = (const float*)d_in[22];
    const float* cdW = (const float*)d_in[23];
    const float* cdB = (const float*)d_in[24];
    const float* dfW = (const float*)d_in[25];
    const float* dfB = (const float*)d_in[26];
    float* out = (float*)d_out;

    float* S = nullptr;
    cudaGetSymbolAddress((void**)&S, g_scratch);
    float* qw    = S + OFF_QW;
    float* dw    = S + OFF_DW;
    float* qbow  = S + OFF_QBOW;
    float* dbow  = S + OFF_DBOW;
    float* qu    = S + OFF_QU;
    float* qb    = S + OFF_QB;
    float* qt    = S + OFF_QT;
    float* du    = S + OFF_DU;
    float* db    = S + OFF_DB;
    float* dt    = S + OFF_DT;
    float* qs    = S + OFF_QS;
    float* ds    = S + OFF_DS;
    float* cs1   = S + OFF_CS1;
    float* cs8   = S + OFF_CS8;
    float* partP = S + OFF_PART;

    gather_kernel<<<(BB * LQ * 75 + 255) / 256, 256>>>(wrd, qwt, qw, BB * LQ);
    gather_kernel<<<(BB * LD * 75 + 255) / 256, 256>>>(wrd, dwt, dw, BB * LD);

    colsum_kernel<<<dim3(1, BB), 128>>>(qw, LQ, 20, cs1);
    colsum_kernel<<<dim3(8, BB), 128>>>(dw, LD, 64, cs8);
    bow2_kernel<<<BB, 128>>>(cs1, 1, LQ, bowW, bowB, qbow);
    bow2_kernel<<<BB, 128>>>(cs8, 8, LD, bowW, bowB, dbow);

    entity_kernel<<<dim3(EQ, BB), 128>>>(qei, qet, qew, qbow, wrd, ent, car, cdW, cdB, EQ, qs);
    entity_kernel<<<dim3(ED, BB), 128>>>(dei, det, dew, dbow, wrd, ent, car, cdW, cdB, ED, ds);

    wordconv2_kernel<1><<<dim3(1, BB), 128>>>(qw, LQ, 20, cuW, cuB, qu);
    wordconv2_kernel<2><<<dim3(1, BB), 128>>>(qw, LQ, 19, cbW, cbB, qb);
    wordconv2_kernel<3><<<dim3(1, BB), 128>>>(qw, LQ, 18, ctW, ctB, qt);
    wordconv2_kernel<1><<<dim3(16, BB), 128>>>(dw, LD, 512, cuW, cuB, du);
    wordconv2_kernel<2><<<dim3(16, BB), 128>>>(dw, LD, 511, cbW, cbB, db);
    wordconv2_kernel<3><<<dim3(16, BB), 128>>>(dw, LD, 510, ctW, ctB, dt);

    // fused pooling: each D matrix scored against all 62 q rows at once
    pool_fused_kernel<<<dim3(4, BB), 256>>>(qu, qb, qt, qs, du, 512, dwm, 512, 128,  0, partP);
    pool_fused_kernel<<<dim3(4, BB), 256>>>(qu, qb, qt, qs, db, 511, dwm, 512, 128,  4, partP);
    pool_fused_kernel<<<dim3(4, BB), 256>>>(qu, qb, qt, qs, dt, 510, dwm, 512, 128,  8, partP);
    pool_fused_kernel<<<dim3(1, BB), 256>>>(qu, qb, qt, qs, ds,  10, dem,  10,  16, 12, partP);

    final_kernel<<<BB, 256>>>(partP, qwm, qem, dfW, dfB, out);
}

// round 3
// speedup vs baseline: 1.6310x; 1.0284x over previous
#include <cuda_runtime.h>
#include <cstdint>
#include <math.h>

// ---------------- problem constants ----------------
constexpr int BB = 64, LQ = 20, LD = 512, DIM = 300, NB = 11, WIN = 5;
constexpr int EQ = 5, ED = 10, DESC = 20, KC = 10;
constexpr int CH = 128;
constexpr int NPAIR = 16;
constexpr int QR_TOT = 64;     // 62 real q rows (20+19+18+5) padded to 64
constexpr int PSLOTS = 13;     // 4 chunks x 3 big D mats + 1 for ds
constexpr int NCD = 16;        // colsum chunks for doc

__constant__ float c_mu[NB]  = {1.0f, 0.9f, 0.7f, 0.5f, 0.3f, 0.1f, -0.1f, -0.3f, -0.5f, -0.7f, -0.9f};
// -0.5 / sigma^2
__constant__ float c_nis[NB] = {-500000.0f, -50.0f, -50.0f, -50.0f, -50.0f, -50.0f, -50.0f, -50.0f, -50.0f, -50.0f, -50.0f};

// pair -> (q source, d source) per reference pools order
__constant__ int c_pq[NPAIR]  = {0,0,0,1,2,1,1,2,2,3,3,3,0,1,2,3};
__constant__ int c_pd[NPAIR]  = {0,2,1,0,0,1,2,1,2,0,1,2,3,3,3,3};
__constant__ int c_qoff[4]    = {0,20,39,57};
__constant__ int c_qlen[4]    = {20,19,18,5};
__constant__ int c_dslot[4]   = {0,4,8,12};
__constant__ int c_dnch[4]    = {4,4,4,1};

// ---------------- scratch layout ----------------
constexpr size_t OFF_QW   = 0;                                   // B*LQ*300
constexpr size_t OFF_DW   = OFF_QW   + (size_t)BB*LQ*DIM;        // B*LD*300
constexpr size_t OFF_QBOW = OFF_DW   + (size_t)BB*LD*DIM;        // B*128
constexpr size_t OFF_DBOW = OFF_QBOW + (size_t)BB*CH;
constexpr size_t OFF_QU   = OFF_DBOW + (size_t)BB*CH;            // B*20*128
constexpr size_t OFF_QB   = OFF_QU   + (size_t)BB*20*CH;         // B*19*128
constexpr size_t OFF_QT   = OFF_QB   + (size_t)BB*19*CH;         // B*18*128
constexpr size_t OFF_DU   = OFF_QT   + (size_t)BB*18*CH;         // B*512*128
constexpr size_t OFF_DB   = OFF_DU   + (size_t)BB*512*CH;        // B*511*128
constexpr size_t OFF_DT   = OFF_DB   + (size_t)BB*511*CH;        // B*510*128
constexpr size_t OFF_QS   = OFF_DT   + (size_t)BB*510*CH;        // B*5*128
constexpr size_t OFF_DS   = OFF_QS   + (size_t)BB*EQ*CH;         // B*10*128
constexpr size_t OFF_CS1  = OFF_DS   + (size_t)BB*ED*CH;         // B*300     (q colsum)
constexpr size_t OFF_CS8  = OFF_CS1  + (size_t)BB*DIM;           // B*16*300  (d colsum)
constexpr size_t OFF_PART = OFF_CS8  + (size_t)BB*NCD*DIM;       // 13*B*64*11
constexpr size_t SCRATCH_TOTAL = OFF_PART + (size_t)PSLOTS*BB*QR_TOT*NB;

__device__ float g_scratch[SCRATCH_TOTAL];

// ---------------- gather: out[r,:] = emb[tok[r],:]  (300 floats = 75 float4) ----------------
__global__ void gather_kernel(const float* __restrict__ emb, const int* __restrict__ tok,
                              float* __restrict__ out, int nrows) {
    int idx = blockIdx.x * blockDim.x + threadIdx.x;
    int total = nrows * 75;
    if (idx >= total) return;
    int r = idx / 75, c = idx - r * 75;
    reinterpret_cast<float4*>(out)[idx] =
        reinterpret_cast<const float4*>(emb)[(size_t)tok[r] * 75 + c];
}

// ---------------- column-sum partials: out[b,c,d] = sum over rows chunk c ----------------
__global__ void colsum_kernel(const float* __restrict__ X, int L, int rows,
                              float* __restrict__ outp) {
    int c = blockIdx.x, b = blockIdx.y;
    int NC = gridDim.x;
    int t = threadIdx.x;
    int r0 = c * rows;
    for (int d = t; d < DIM; d += blockDim.x) {
        float s = 0.f;
        #pragma unroll 4
        for (int r = 0; r < rows; r++) {
            int row = r0 + r;
            if (row < L) s += X[((size_t)b * L + row) * DIM + d];
        }
        outp[((size_t)b * NC + c) * DIM + d] = s;
    }
}

// ---------------- bow stage2: reduce partials + matvec with bow_W ----------------
__global__ void bow2_kernel(const float* __restrict__ partS, int NC, int L,
                            const float* __restrict__ W, const float* __restrict__ bias,
                            float* __restrict__ out) {
    int b = blockIdx.x, o = threadIdx.x;   // 128 threads
    __shared__ float ssum[DIM];
    for (int d = o; d < DIM; d += CH) {
        float s = 0.f;
        for (int c = 0; c < NC; c++) s += partS[((size_t)b * NC + c) * DIM + d];
        ssum[d] = s;
    }
    __syncthreads();
    float acc = 0.f;
    const float* wr = W + (size_t)o * DIM;
    #pragma unroll 4
    for (int d = 0; d < DIM; d++) acc += ssum[d] * wr[d];
    out[b * CH + o] = acc + (float)L * bias[o];
}

// ---------------- word conv: float4-j register-blocked, 4ch x 8pos per thread ----------------
// 128 threads: cg = t&31 (channels cg,cg+32,cg+64,cg+96), pg = t>>5 (positions pg*8..pg*8+7).
// LT = 32 positions per block. d-dim tiled by DC=20, j vectorized by 4 (LDS.128).
template <int K>
__global__ void __launch_bounds__(128) wordconv3_kernel(
        const float* __restrict__ X, int L, int Lout,
        const float* __restrict__ W, const float* __restrict__ bias,
        float* __restrict__ out) {
    constexpr int DC = 20;                              // d-chunk (mult of 4, divides 300)
    constexpr int KD = K * DC;
    constexpr int WST = (K == 1) ? 20 : (K == 2) ? 44 : 68;  // stride: mult4, odd*4 mod 32
    constexpr int LT = 32;
    constexpr int XR = LT + K - 1;
    __shared__ alignas(16) float Ws[CH * WST];
    __shared__ alignas(16) float Xs[XR * DC];

    int n = blockIdx.y;
    int l0 = blockIdx.x * LT;
    int t = threadIdx.x;
    int cg = t & 31, pg = t >> 5;

    float acc[4][8];
    #pragma unroll
    for (int u = 0; u < 4; u++)
        #pragma unroll
        for (int r = 0; r < 8; r++) acc[u][r] = 0.f;

    for (int d0 = 0; d0 < DIM; d0 += DC) {
        __syncthreads();
        for (int i = t; i < CH * KD; i += 128) {
            int ch = i / KD, kk = i - ch * KD;
            int tap = kk / DC, j = kk - tap * DC;
            Ws[ch * WST + tap * DC + j] = W[(size_t)ch * K * DIM + (size_t)tap * DIM + d0 + j];
        }
        for (int i = t; i < XR * DC; i += 128) {
            int r = i / DC, j = i - r * DC;
            int lg = l0 + r;
            Xs[i] = (lg < L) ? X[((size_t)n * L + lg) * DIM + d0 + j] : 0.f;
        }
        __syncthreads();
        #pragma unroll
        for (int jq = 0; jq < DC / 4; jq++) {
            float4 xr[8 + K - 1];
            #pragma unroll
            for (int r = 0; r < 8 + K - 1; r++)
                xr[r] = *reinterpret_cast<const float4*>(&Xs[(pg * 8 + r) * DC + jq * 4]);
            #pragma unroll
            for (int u = 0; u < 4; u++) {
                #pragma unroll
                for (int tap = 0; tap < K; tap++) {
                    float4 w4 = *reinterpret_cast<const float4*>(
                        &Ws[(cg + 32 * u) * WST + tap * DC + jq * 4]);
                    #pragma unroll
                    for (int r = 0; r < 8; r++) {
                        float a = acc[u][r];
                        a = fmaf(w4.x, xr[r + tap].x, a);
                        a = fmaf(w4.y, xr[r + tap].y, a);
                        a = fmaf(w4.z, xr[r + tap].z, a);
                        a = fmaf(w4.w, xr[r + tap].w, a);
                        acc[u][r] = a;
                    }
                }
            }
        }
    }

    float bvals[4];
    #pragma unroll
    for (int u = 0; u < 4; u++) bvals[u] = bias[cg + 32 * u];

    #pragma unroll
    for (int r = 0; r < 8; r++) {
        int p = pg * 8 + r;
        float v[4];
        float ss = 0.f;
        #pragma unroll
        for (int u = 0; u < 4; u++) {
            v[u] = fmaxf(acc[u][r] + bvals[u], 0.f);
            ss += v[u] * v[u];
        }
        #pragma unroll
        for (int off = 16; off > 0; off >>= 1) ss += __shfl_xor_sync(0xffffffffu, ss, off);
        float inv = 1.f / fmaxf(sqrtf(ss), 1e-10f);
        if (l0 + p < Lout) {
            float* op = out + ((size_t)n * Lout + l0 + p) * CH;
            #pragma unroll
            for (int u = 0; u < 4; u++) op[cg + 32 * u] = v[u] * inv;
        }
    }
}

// ---------------- entity branch: desc conv(max) + carrier attention + ent emb, L2 norm ----------------
__global__ void __launch_bounds__(128) entity_kernel(
        const int* __restrict__ ids_e, const int* __restrict__ ids_desc,
        const int* __restrict__ ids_car, const float* __restrict__ bow,
        const float* __restrict__ wrd_emb, const float* __restrict__ ent_emb,
        const float* __restrict__ car_emb,
        const float* __restrict__ W, const float* __restrict__ bias,
        int n_ent, float* __restrict__ out) {
    constexpr int K = WIN, DC = 12, LT = 16, WST = 60;  // 60 mod 32 = 28 = 4*7: conflict-free
    __shared__ alignas(16) float Ws[CH * WST];
    __shared__ alignas(16) float Xs[DESC * DC];
    __shared__ int toks[DESC];
    __shared__ int crows[KC];
    __shared__ float bv[CH];
    __shared__ float logits[KC];
    __shared__ float att[KC];
    __shared__ float red[4];

    int e = blockIdx.x, b = blockIdx.y;
    int o = threadIdx.x;
    int warp = o >> 5, lane = o & 31;

    if (o < DESC) toks[o] = ids_desc[(size_t)b * n_ent * DESC + e * DESC + o];
    if (o < KC)   crows[o] = ids_car[(size_t)b * n_ent * KC + e * KC + o];
    bv[o] = bow[b * CH + o];
    __syncthreads();

    float acc[LT];
    #pragma unroll
    for (int p = 0; p < LT; p++) acc[p] = 0.f;

    for (int d0 = 0; d0 < DIM; d0 += DC) {
        for (int i = o; i < CH * (K * DC); i += CH) {
            int oc = i / (K * DC), kk = i - oc * (K * DC);
            int tap = kk / DC, j = kk - tap * DC;
            Ws[oc * WST + tap * DC + j] = W[(size_t)oc * K * DIM + (size_t)tap * DIM + d0 + j];
        }
        for (int i = o; i < DESC * DC; i += CH) {
            int r = i / DC, j = i - r * DC;
            Xs[i] = wrd_emb[(size_t)toks[r] * DIM + d0 + j];
        }
        __syncthreads();
        #pragma unroll
        for (int jq = 0; jq < DC / 4; jq++) {
            float4 xr[DESC];
            #pragma unroll
            for (int r = 0; r < DESC; r++)
                xr[r] = *reinterpret_cast<const float4*>(&Xs[r * DC + jq * 4]);
            #pragma unroll
            for (int tap = 0; tap < K; tap++) {
                float4 w4 = *reinterpret_cast<const float4*>(&Ws[o * WST + tap * DC + jq * 4]);
                #pragma unroll
                for (int p = 0; p < LT; p++) {
                    float a = acc[p];
                    a = fmaf(w4.x, xr[p + tap].x, a);
                    a = fmaf(w4.y, xr[p + tap].y, a);
                    a = fmaf(w4.z, xr[p + tap].z, a);
                    a = fmaf(w4.w, xr[p + tap].w, a);
                    acc[p] = a;
                }
            }
        }
        __syncthreads();
    }
    float bo = bias[o];
    float econv = 0.f;
    #pragma unroll
    for (int p = 0; p < LT; p++) econv = fmaxf(econv, fmaxf(acc[p] + bo, 0.f));

    if (o < KC) {
        const float* cr = car_emb + (size_t)crows[o] * CH;
        float s = 0.f;
        #pragma unroll 4
        for (int c = 0; c < CH; c++) s += bv[c] * cr[c];
        logits[o] = s;
    }
    __syncthreads();
    if (o == 0) {
        float mx = -1e30f;
        #pragma unroll
        for (int k = 0; k < KC; k++) mx = fmaxf(mx, logits[k]);
        float ssum = 0.f;
        #pragma unroll
        for (int k = 0; k < KC; k++) { float ev = __expf(logits[k] - mx); att[k] = ev; ssum += ev; }
        float inv = 1.f / ssum;
        #pragma unroll
        for (int k = 0; k < KC; k++) att[k] *= inv;
    }
    __syncthreads();
    float ew = 0.f;
    #pragma unroll
    for (int k = 0; k < KC; k++) ew += att[k] * car_emb[(size_t)crows[k] * CH + o];

    float v = ent_emb[(size_t)ids_e[b * n_ent + e] * CH + o] + econv + ew;

    float ss = v * v;
    #pragma unroll
    for (int off = 16; off > 0; off >>= 1) ss += __shfl_xor_sync(0xffffffffu, ss, off);
    if (lane == 0) red[warp] = ss;
    __syncthreads();
    float tot = red[0] + red[1] + red[2] + red[3];
    float inv = 1.f / fmaxf(sqrtf(tot), 1e-10f);
    out[((size_t)b * n_ent + e) * CH + o] = v * inv;
}

// ---------------- fused kernel pooling: one D matrix vs ALL 62 q rows ----------------
__global__ void __launch_bounds__(256) pool_fused_kernel(
        const float* __restrict__ Qu, const float* __restrict__ Qb,
        const float* __restrict__ Qt, const float* __restrict__ Qs,
        const float* __restrict__ D, int Ld,
        const float* __restrict__ md, int md_stride,
        int chunkRows, int slotBase, float* __restrict__ part) {
    int chunk = blockIdx.x, b = blockIdx.y;
    int t = threadIdx.x;
    int qr = t >> 2, g = t & 3;

    // load this thread's 32 q dims into registers
    float4 qreg[8];
    const float* qptr = nullptr;
    if (qr < 20)      qptr = Qu + (size_t)(b * 20 + qr) * CH;
    else if (qr < 39) qptr = Qb + (size_t)(b * 19 + (qr - 20)) * CH;
    else if (qr < 57) qptr = Qt + (size_t)(b * 18 + (qr - 39)) * CH;
    else if (qr < 62) qptr = Qs + (size_t)(b * 5 + (qr - 57)) * CH;
    if (qptr) {
        const float4* q4 = reinterpret_cast<const float4*>(qptr);
        #pragma unroll
        for (int i = 0; i < 8; i++) qreg[i] = q4[g + 4 * i];
    } else {
        #pragma unroll
        for (int i = 0; i < 8; i++) qreg[i] = make_float4(0.f, 0.f, 0.f, 0.f);
    }

    float mu0 = c_mu[g],     ni0 = c_nis[g];
    float mu1 = c_mu[g + 4], ni1 = c_nis[g + 4];
    float mu2 = 0.f, ni2 = 0.f;
    bool has2 = (g + 8) < NB;
    if (has2) { mu2 = c_mu[g + 8]; ni2 = c_nis[g + 8]; }

    float acc0 = 0.f, acc1 = 0.f, acc2 = 0.f;

    __shared__ alignas(16) float Ds[16][CH];
    __shared__ float msk[16];

    int ld_begin = chunk * chunkRows;
    for (int ld0 = ld_begin; ld0 < ld_begin + chunkRows; ld0 += 16) {
        __syncthreads();
        {
            #pragma unroll
            for (int i = t; i < 512; i += 256) {
                int r = i >> 5, c = i & 31;
                int row = ld0 + r;
                float4 v = make_float4(0.f, 0.f, 0.f, 0.f);
                if (row < Ld)
                    v = reinterpret_cast<const float4*>(D + ((size_t)b * Ld + row) * CH)[c];
                reinterpret_cast<float4*>(&Ds[r][0])[c] = v;
            }
            if (t < 16) {
                int rr = ld0 + t;
                msk[t] = (rr < Ld) ? md[(size_t)b * md_stride + rr] : 0.f;
            }
        }
        __syncthreads();
        #pragma unroll
        for (int r = 0; r < 16; r++) {
            const float4* dp = reinterpret_cast<const float4*>(&Ds[r][0]);
            float s = 0.f;
            #pragma unroll
            for (int i = 0; i < 8; i++) {
                float4 d4 = dp[g + 4 * i];
                float4 q4 = qreg[i];
                s += d4.x * q4.x + d4.y * q4.y + d4.z * q4.z + d4.w * q4.w;
            }
            s += __shfl_xor_sync(0xffffffffu, s, 1);
            s += __shfl_xor_sync(0xffffffffu, s, 2);
            float m = msk[r];
            float dd0 = s - mu0; acc0 += m * __expf(dd0 * dd0 * ni0);
            float dd1 = s - mu1; acc1 += m * __expf(dd1 * dd1 * ni1);
            if (has2) { float dd2 = s - mu2; acc2 += m * __expf(dd2 * dd2 * ni2); }
        }
    }

    size_t base = ((size_t)(slotBase + chunk) * BB + b) * (QR_TOT * NB) + (size_t)qr * NB;
    part[base + g]     = acc0;
    part[base + g + 4] = acc1;
    if (has2) part[base + g + 8] = acc2;
}

// ---------------- final: reduce chunk partials, log, mask, dense dot, tanh ----------------
__global__ void __launch_bounds__(256) final_kernel(
        const float* __restrict__ part, const float* __restrict__ qwm,
        const float* __restrict__ qem, const float* __restrict__ dW,
        const float* __restrict__ dB, float* __restrict__ out) {
    int b = blockIdx.x, t = threadIdx.x;
    float local = 0.f;
    for (int p = 0; p < NPAIR; p++) {
        int qsrc = c_pq[p], dmat = c_pd[p];
        int Lqp = c_qlen[qsrc], off = c_qoff[qsrc];
        int slot = c_dslot[dmat], nch = c_dnch[dmat];
        int tot = Lqp * NB;
        for (int idx = t; idx < tot; idx += 256) {
            int lq = idx / NB, k = idx - lq * NB;
            int row = off + lq;
            float s = 0.f;
            for (int c = 0; c < nch; c++)
                s += part[((size_t)(slot + c) * BB + b) * (QR_TOT * NB) + row * NB + k];
            float mq = (qsrc < 3) ? qwm[b * 20 + lq] : qem[b * 5 + lq];
            local += dW[p * NB + k] * (__logf(fmaxf(s, 1e-10f)) * 0.01f * mq);
        }
    }
    #pragma unroll
    for (int off = 16; off > 0; off >>= 1) local += __shfl_xor_sync(0xffffffffu, local, off);
    __shared__ float r8[8];
    if ((t & 31) == 0) r8[t >> 5] = local;
    __syncthreads();
    if (t == 0) {
        float s = 0.f;
        #pragma unroll
        for (int w = 0; w < 8; w++) s += r8[w];
        out[b] = tanhf(s + dB[0]);
    }
}

// ---------------- launcher ----------------
extern "C" void kernel_launch(void* const* d_in, const int* in_sizes, int n_in,
                              void* d_out, int out_size) {
    const int*   qwt = (const int*)d_in[0];
    const float* qwm = (const float*)d_in[1];
    const int*   qei = (const int*)d_in[2];
    const int*   qet = (const int*)d_in[3];
    const int*   qew = (const int*)d_in[4];
    const float* qem = (const float*)d_in[5];
    const int*   dwt = (const int*)d_in[6];
    const float* dwm = (const float*)d_in[7];
    const int*   dei = (const int*)d_in[8];
    const int*   det = (const int*)d_in[9];
    const int*   dew = (const int*)d_in[10];
    const float* dem = (const float*)d_in[11];
    const float* wrd = (const float*)d_in[12];
    const float* ent = (const float*)d_in[13];
    const float* car = (const float*)d_in[14];
    const float* bowW = (const float*)d_in[15];
    const float* bowB = (const float*)d_in[16];
    const float* cuW = (const float*)d_in[17];
    const float* cuB = (const float*)d_in[18];
    const float* cbW = (const float*)d_in[19];
    const float* cbB = (const float*)d_in[20];
    const float* ctW = (const float*)d_in[21];
    const float* ctB = (const float*)d_in[22];
    const float* cdW = (const float*)d_in[23];
    const float* cdB = (const float*)d_in[24];
    const float* dfW = (const float*)d_in[25];
    const float* dfB = (const float*)d_in[26];
    float* out = (float*)d_out;

    float* S = nullptr;
    cudaGetSymbolAddress((void**)&S, g_scratch);
    float* qw    = S + OFF_QW;
    float* dw    = S + OFF_DW;
    float* qbow  = S + OFF_QBOW;
    float* dbow  = S + OFF_DBOW;
    float* qu    = S + OFF_QU;
    float* qb    = S + OFF_QB;
    float* qt    = S + OFF_QT;
    float* du    = S + OFF_DU;
    float* db    = S + OFF_DB;
    float* dt    = S + OFF_DT;
    float* qs    = S + OFF_QS;
    float* ds    = S + OFF_DS;
    float* cs1   = S + OFF_CS1;
    float* cs8   = S + OFF_CS8;
    float* partP = S + OFF_PART;

    // launches 1-5
    gather_kernel<<<(BB * LQ * 75 + 255) / 256, 256>>>(wrd, qwt, qw, BB * LQ);
    gather_kernel<<<(BB * LD * 75 + 255) / 256, 256>>>(wrd, dwt, dw, BB * LD);
    colsum_kernel<<<dim3(1, BB), 128>>>(qw, LQ, 20, cs1);
    colsum_kernel<<<dim3(NCD, BB), 128>>>(dw, LD, LD / NCD, cs8);
    bow2_kernel<<<BB, 128>>>(cs1, 1, LQ, bowW, bowB, qbow);

    // launch 6: profiled by ncu (-s 5 -c 1) — the big K=3 doc conv
    wordconv3_kernel<3><<<dim3(16, BB), 128>>>(dw, LD, 510, ctW, ctB, dt);

    bow2_kernel<<<BB, 128>>>(cs8, NCD, LD, bowW, bowB, dbow);
    entity_kernel<<<dim3(EQ, BB), 128>>>(qei, qet, qew, qbow, wrd, ent, car, cdW, cdB, EQ, qs);
    entity_kernel<<<dim3(ED, BB), 128>>>(dei, det, dew, dbow, wrd, ent, car, cdW, cdB, ED, ds);

    wordconv3_kernel<1><<<dim3(1, BB), 128>>>(qw, LQ, 20, cuW, cuB, qu);
    wordconv3_kernel<2><<<dim3(1, BB), 128>>>(qw, LQ, 19, cbW, cbB, qb);
    wordconv3_kernel<3><<<dim3(1, BB), 128>>>(qw, LQ, 18, ctW, ctB, qt);
    wordconv3_kernel<1><<<dim3(16, BB), 128>>>(dw, LD, 512, cuW, cuB, du);
    wordconv3_kernel<2><<<dim3(16, BB), 128>>>(dw, LD, 511, cbW, cbB, db);

    // fused pooling: each D matrix scored against all 62 q rows at once
    pool_fused_kernel<<<dim3(4, BB), 256>>>(qu, qb, qt, qs, du, 512, dwm, 512, 128,  0, partP);
    pool_fused_kernel<<<dim3(4, BB), 256>>>(qu, qb, qt, qs, db, 511, dwm, 512, 128,  4, partP);
    pool_fused_kernel<<<dim3(4, BB), 256>>>(qu, qb, qt, qs, dt, 510, dwm, 512, 128,  8, partP);
    pool_fused_kernel<<<dim3(1, BB), 256>>>(qu, qb, qt, qs, ds,  10, dem,  10,  16, 12, partP);

    final_kernel<<<BB, 256>>>(partP, qwm, qem, dfW, dfB, out);
}

// round 4
// speedup vs baseline: 2.7498x; 1.6860x over previous
#include <cuda_runtime.h>
#include <cstdint>
#include <math.h>

// ---------------- problem constants ----------------
constexpr int BB = 64, LQ = 20, LD = 512, DIM = 300, NB = 11, WIN = 5;
constexpr int EQ = 5, ED = 10, DESC = 20, KC = 10;
constexpr int CH = 128;
constexpr int NPAIR = 16;
constexpr int QR_TOT = 64;     // 62 real q rows (20+19+18+5) padded to 64
constexpr int PSLOTS = 13;     // 4 chunks x 3 big D mats + 1 for ds
constexpr int NCD = 16;        // colsum chunks for doc

__constant__ float c_mu[NB]  = {1.0f, 0.9f, 0.7f, 0.5f, 0.3f, 0.1f, -0.1f, -0.3f, -0.5f, -0.7f, -0.9f};
// -0.5 / sigma^2
__constant__ float c_nis[NB] = {-500000.0f, -50.0f, -50.0f, -50.0f, -50.0f, -50.0f, -50.0f, -50.0f, -50.0f, -50.0f, -50.0f};

// pair -> (q source, d source) per reference pools order
__constant__ int c_pq[NPAIR]  = {0,0,0,1,2,1,1,2,2,3,3,3,0,1,2,3};
__constant__ int c_pd[NPAIR]  = {0,2,1,0,0,1,2,1,2,0,1,2,3,3,3,3};
__constant__ int c_qoff[4]    = {0,20,39,57};
__constant__ int c_qlen[4]    = {20,19,18,5};
__constant__ int c_dslot[4]   = {0,4,8,12};
__constant__ int c_dnch[4]    = {4,4,4,1};

// ---------------- scratch layout ----------------
constexpr size_t OFF_QW   = 0;                                   // B*LQ*300
constexpr size_t OFF_DW   = OFF_QW   + (size_t)BB*LQ*DIM;        // B*LD*300
constexpr size_t OFF_QBOW = OFF_DW   + (size_t)BB*LD*DIM;        // B*128
constexpr size_t OFF_DBOW = OFF_QBOW + (size_t)BB*CH;
constexpr size_t OFF_QU   = OFF_DBOW + (size_t)BB*CH;            // B*20*128
constexpr size_t OFF_QB   = OFF_QU   + (size_t)BB*20*CH;         // B*19*128
constexpr size_t OFF_QT   = OFF_QB   + (size_t)BB*19*CH;         // B*18*128
constexpr size_t OFF_DU   = OFF_QT   + (size_t)BB*18*CH;         // B*512*128
constexpr size_t OFF_DB   = OFF_DU   + (size_t)BB*512*CH;        // B*511*128
constexpr size_t OFF_DT   = OFF_DB   + (size_t)BB*511*CH;        // B*510*128
constexpr size_t OFF_QS   = OFF_DT   + (size_t)BB*510*CH;        // B*5*128
constexpr size_t OFF_DS   = OFF_QS   + (size_t)BB*EQ*CH;         // B*10*128
constexpr size_t OFF_CS1  = OFF_DS   + (size_t)BB*ED*CH;         // B*300     (q colsum)
constexpr size_t OFF_CS8  = OFF_CS1  + (size_t)BB*DIM;           // B*16*300  (d colsum)
constexpr size_t OFF_PART = OFF_CS8  + (size_t)BB*NCD*DIM;       // 13*B*64*11
constexpr size_t SCRATCH_TOTAL = OFF_PART + (size_t)PSLOTS*BB*QR_TOT*NB;

__device__ float g_scratch[SCRATCH_TOTAL];

// ---------------- gather: out[r,:] = emb[tok[r],:]  (300 floats = 75 float4) ----------------
__global__ void gather_kernel(const float* __restrict__ emb, const int* __restrict__ tok,
                              float* __restrict__ out, int nrows) {
    int idx = blockIdx.x * blockDim.x + threadIdx.x;
    int total = nrows * 75;
    if (idx >= total) return;
    int r = idx / 75, c = idx - r * 75;
    reinterpret_cast<float4*>(out)[idx] =
        reinterpret_cast<const float4*>(emb)[(size_t)tok[r] * 75 + c];
}

// ---------------- column-sum partials: out[b,c,d] = sum over rows chunk c ----------------
__global__ void colsum_kernel(const float* __restrict__ X, int L, int rows,
                              float* __restrict__ outp) {
    int c = blockIdx.x, b = blockIdx.y;
    int NC = gridDim.x;
    int t = threadIdx.x;
    int r0 = c * rows;
    for (int d = t; d < DIM; d += blockDim.x) {
        float s = 0.f;
        #pragma unroll 4
        for (int r = 0; r < rows; r++) {
            int row = r0 + r;
            if (row < L) s += X[((size_t)b * L + row) * DIM + d];
        }
        outp[((size_t)b * NC + c) * DIM + d] = s;
    }
}

// ---------------- bow stage2: reduce partials + matvec with bow_W ----------------
__global__ void bow2_kernel(const float* __restrict__ partS, int NC, int L,
                            const float* __restrict__ W, const float* __restrict__ bias,
                            float* __restrict__ out) {
    int b = blockIdx.x, o = threadIdx.x;   // 128 threads
    __shared__ float ssum[DIM];
    for (int d = o; d < DIM; d += CH) {
        float s = 0.f;
        for (int c = 0; c < NC; c++) s += partS[((size_t)b * NC + c) * DIM + d];
        ssum[d] = s;
    }
    __syncthreads();
    float acc = 0.f;
    const float* wr = W + (size_t)o * DIM;
    #pragma unroll 4
    for (int d = 0; d < DIM; d++) acc += ssum[d] * wr[d];
    out[b * CH + o] = acc + (float)L * bias[o];
}

// ---------------- word conv merged doc+query: 256 threads, LT=64 positions ----------------
// cg = t&31 (channels cg,cg+32,cg+64,cg+96), pg = t>>5 in [0,8) (positions pg*8..pg*8+7).
// blockIdx.x < blocksD -> doc tile; == blocksD -> query tile (whole query in one block).
template <int K>
__global__ void __launch_bounds__(256) wordconv4_kernel(
        const float* __restrict__ Xd, int Ld_, int Loutd,
        const float* __restrict__ Xq, int Loutq,
        const float* __restrict__ W, const float* __restrict__ bias,
        float* __restrict__ outd, float* __restrict__ outq, int blocksD) {
    constexpr int DC = 20;                              // d-chunk (mult of 4, divides 300)
    constexpr int WST = (K == 1) ? 20 : (K == 2) ? 44 : 68;  // conflict-free strides
    constexpr int LT = 64;
    constexpr int XR = LT + K - 1;
    __shared__ alignas(16) float Ws[CH * WST];
    __shared__ alignas(16) float Xs[XR * DC];

    int n = blockIdx.y;
    bool isQ = ((int)blockIdx.x >= blocksD);
    const float* X = isQ ? Xq : Xd;
    int L    = isQ ? LQ : Ld_;
    int Lout = isQ ? Loutq : Loutd;
    float* out = isQ ? outq : outd;
    int l0 = isQ ? 0 : blockIdx.x * LT;

    int t = threadIdx.x;
    int cg = t & 31, pg = t >> 5;

    float acc[4][8];
    #pragma unroll
    for (int u = 0; u < 4; u++)
        #pragma unroll
        for (int r = 0; r < 8; r++) acc[u][r] = 0.f;

    for (int d0 = 0; d0 < DIM; d0 += DC) {
        __syncthreads();
        // weight tile, float4 loads: CH*K*5 quads
        for (int i = t; i < CH * K * 5; i += 256) {
            int ch = i / (K * 5), rem = i - ch * (K * 5);
            int tap = rem / 5, q = rem - tap * 5;
            *reinterpret_cast<float4*>(&Ws[ch * WST + tap * DC + q * 4]) =
                *reinterpret_cast<const float4*>(&W[(size_t)ch * K * DIM + (size_t)tap * DIM + d0 + q * 4]);
        }
        // input tile, float4 loads: XR*5 quads
        for (int i = t; i < XR * 5; i += 256) {
            int r = i / 5, q = i - r * 5;
            int lg = l0 + r;
            float4 v = make_float4(0.f, 0.f, 0.f, 0.f);
            if (lg < L)
                v = *reinterpret_cast<const float4*>(&X[((size_t)n * L + lg) * DIM + d0 + q * 4]);
            *reinterpret_cast<float4*>(&Xs[r * DC + q * 4]) = v;
        }
        __syncthreads();
        #pragma unroll
        for (int jq = 0; jq < DC / 4; jq++) {
            float4 xr[8 + K - 1];
            #pragma unroll
            for (int r = 0; r < 8 + K - 1; r++)
                xr[r] = *reinterpret_cast<const float4*>(&Xs[(pg * 8 + r) * DC + jq * 4]);
            #pragma unroll
            for (int u = 0; u < 4; u++) {
                #pragma unroll
                for (int tap = 0; tap < K; tap++) {
                    float4 w4 = *reinterpret_cast<const float4*>(
                        &Ws[(cg + 32 * u) * WST + tap * DC + jq * 4]);
                    #pragma unroll
                    for (int r = 0; r < 8; r++) {
                        float a = acc[u][r];
                        a = fmaf(w4.x, xr[r + tap].x, a);
                        a = fmaf(w4.y, xr[r + tap].y, a);
                        a = fmaf(w4.z, xr[r + tap].z, a);
                        a = fmaf(w4.w, xr[r + tap].w, a);
                        acc[u][r] = a;
                    }
                }
            }
        }
    }

    float bvals[4];
    #pragma unroll
    for (int u = 0; u < 4; u++) bvals[u] = bias[cg + 32 * u];

    #pragma unroll
    for (int r = 0; r < 8; r++) {
        int p = pg * 8 + r;
        float v[4];
        float ss = 0.f;
        #pragma unroll
        for (int u = 0; u < 4; u++) {
            v[u] = fmaxf(acc[u][r] + bvals[u], 0.f);
            ss += v[u] * v[u];
        }
        #pragma unroll
        for (int off = 16; off > 0; off >>= 1) ss += __shfl_xor_sync(0xffffffffu, ss, off);
        float inv = 1.f / fmaxf(sqrtf(ss), 1e-10f);
        if (l0 + p < Lout) {
            float* op = out + ((size_t)n * Lout + l0 + p) * CH;
            #pragma unroll
            for (int u = 0; u < 4; u++) op[cg + 32 * u] = v[u] * inv;
        }
    }
}

// ---------------- entity branch merged q+d: desc conv(max) + attention + L2 ----------------
__global__ void __launch_bounds__(128) entity2_kernel(
        const int* __restrict__ qei, const int* __restrict__ qet, const int* __restrict__ qew,
        const float* __restrict__ qbow,
        const int* __restrict__ dei, const int* __restrict__ det, const int* __restrict__ dew,
        const float* __restrict__ dbow,
        const float* __restrict__ wrd_emb, const float* __restrict__ ent_emb,
        const float* __restrict__ car_emb,
        const float* __restrict__ W, const float* __restrict__ bias,
        float* __restrict__ qs_out, float* __restrict__ ds_out) {
    constexpr int K = WIN, DC = 12, LT = 16, WST = 60;
    __shared__ alignas(16) float Ws[CH * WST];
    __shared__ alignas(16) float Xs[DESC * DC];
    __shared__ int toks[DESC];
    __shared__ int crows[KC];
    __shared__ float bv[CH];
    __shared__ float logits[KC];
    __shared__ float att[KC];
    __shared__ float red[4];

    int eg = blockIdx.x, b = blockIdx.y;
    bool isQ = (eg < EQ);
    int e = isQ ? eg : eg - EQ;
    int n_ent = isQ ? EQ : ED;
    const int* ids_e   = isQ ? qei : dei;
    const int* ids_desc= isQ ? qet : det;
    const int* ids_car = isQ ? qew : dew;
    const float* bow   = isQ ? qbow : dbow;
    float* out         = isQ ? qs_out : ds_out;

    int o = threadIdx.x;
    int warp = o >> 5, lane = o & 31;

    if (o < DESC) toks[o] = ids_desc[(size_t)b * n_ent * DESC + e * DESC + o];
    if (o < KC)   crows[o] = ids_car[(size_t)b * n_ent * KC + e * KC + o];
    bv[o] = bow[b * CH + o];
    __syncthreads();

    float acc[LT];
    #pragma unroll
    for (int p = 0; p < LT; p++) acc[p] = 0.f;

    for (int d0 = 0; d0 < DIM; d0 += DC) {
        for (int i = o; i < CH * K * 3; i += CH) {   // float4 quads: K*DC/4 = 15 per ch
            int ch = i / (K * 3), rem = i - ch * (K * 3);
            int tap = rem / 3, q = rem - tap * 3;
            *reinterpret_cast<float4*>(&Ws[ch * WST + tap * DC + q * 4]) =
                *reinterpret_cast<const float4*>(&W[(size_t)ch * K * DIM + (size_t)tap * DIM + d0 + q * 4]);
        }
        for (int i = o; i < DESC * 3; i += CH) {
            int r = i / 3, q = i - r * 3;
            *reinterpret_cast<float4*>(&Xs[r * DC + q * 4]) =
                *reinterpret_cast<const float4*>(&wrd_emb[(size_t)toks[r] * DIM + d0 + q * 4]);
        }
        __syncthreads();
        #pragma unroll
        for (int jq = 0; jq < DC / 4; jq++) {
            float4 xr[DESC];
            #pragma unroll
            for (int r = 0; r < DESC; r++)
                xr[r] = *reinterpret_cast<const float4*>(&Xs[r * DC + jq * 4]);
            #pragma unroll
            for (int tap = 0; tap < K; tap++) {
                float4 w4 = *reinterpret_cast<const float4*>(&Ws[o * WST + tap * DC + jq * 4]);
                #pragma unroll
                for (int p = 0; p < LT; p++) {
                    float a = acc[p];
                    a = fmaf(w4.x, xr[p + tap].x, a);
                    a = fmaf(w4.y, xr[p + tap].y, a);
                    a = fmaf(w4.z, xr[p + tap].z, a);
                    a = fmaf(w4.w, xr[p + tap].w, a);
                    acc[p] = a;
                }
            }
        }
        __syncthreads();
    }
    float bo = bias[o];
    float econv = 0.f;
    #pragma unroll
    for (int p = 0; p < LT; p++) econv = fmaxf(econv, fmaxf(acc[p] + bo, 0.f));

    if (o < KC) {
        const float* cr = car_emb + (size_t)crows[o] * CH;
        float s = 0.f;
        #pragma unroll 4
        for (int c = 0; c < CH; c++) s += bv[c] * cr[c];
        logits[o] = s;
    }
    __syncthreads();
    if (o == 0) {
        float mx = -1e30f;
        #pragma unroll
        for (int k = 0; k < KC; k++) mx = fmaxf(mx, logits[k]);
        float ssum = 0.f;
        #pragma unroll
        for (int k = 0; k < KC; k++) { float ev = __expf(logits[k] - mx); att[k] = ev; ssum += ev; }
        float inv = 1.f / ssum;
        #pragma unroll
        for (int k = 0; k < KC; k++) att[k] *= inv;
    }
    __syncthreads();
    float ew = 0.f;
    #pragma unroll
    for (int k = 0; k < KC; k++) ew += att[k] * car_emb[(size_t)crows[k] * CH + o];

    float v = ent_emb[(size_t)ids_e[b * n_ent + e] * CH + o] + econv + ew;

    float ss = v * v;
    #pragma unroll
    for (int off = 16; off > 0; off >>= 1) ss += __shfl_xor_sync(0xffffffffu, ss, off);
    if (lane == 0) red[warp] = ss;
    __syncthreads();
    float tot = red[0] + red[1] + red[2] + red[3];
    float inv = 1.f / fmaxf(sqrtf(tot), 1e-10f);
    out[((size_t)b * n_ent + e) * CH + o] = v * inv;
}

// ---------------- fused kernel pooling (single launch): slot = blockIdx.x in [0,13) ----------------
__global__ void __launch_bounds__(256) pool_all_kernel(
        const float* __restrict__ Qu, const float* __restrict__ Qb,
        const float* __restrict__ Qt, const float* __restrict__ Qs,
        const float* __restrict__ Du, const float* __restrict__ Db,
        const float* __restrict__ Dt, const float* __restrict__ Dsm,
        const float* __restrict__ dwm, const float* __restrict__ dem,
        float* __restrict__ part) {
    int slot = blockIdx.x, b = blockIdx.y;
    int dm = slot >> 2;             // 0-3->0, 4-7->1, 8-11->2, 12->3
    int chunk = slot & 3;
    const float* D  = (dm == 0) ? Du : (dm == 1) ? Db : (dm == 2) ? Dt : Dsm;
    int Ld          = (dm == 0) ? 512 : (dm == 1) ? 511 : (dm == 2) ? 510 : 10;
    const float* md = (dm < 3) ? dwm : dem;
    int md_stride   = (dm < 3) ? 512 : 10;
    int chunkRows   = (dm < 3) ? 128 : 16;

    int t = threadIdx.x;
    int qr = t >> 2, g = t & 3;

    float4 qreg[8];
    const float* qptr = nullptr;
    if (qr < 20)      qptr = Qu + (size_t)(b * 20 + qr) * CH;
    else if (qr < 39) qptr = Qb + (size_t)(b * 19 + (qr - 20)) * CH;
    else if (qr < 57) qptr = Qt + (size_t)(b * 18 + (qr - 39)) * CH;
    else if (qr < 62) qptr = Qs + (size_t)(b * 5 + (qr - 57)) * CH;
    if (qptr) {
        const float4* q4 = reinterpret_cast<const float4*>(qptr);
        #pragma unroll
        for (int i = 0; i < 8; i++) qreg[i] = q4[g + 4 * i];
    } else {
        #pragma unroll
        for (int i = 0; i < 8; i++) qreg[i] = make_float4(0.f, 0.f, 0.f, 0.f);
    }

    float mu0 = c_mu[g],     ni0 = c_nis[g];
    float mu1 = c_mu[g + 4], ni1 = c_nis[g + 4];
    float mu2 = 0.f, ni2 = 0.f;
    bool has2 = (g + 8) < NB;
    if (has2) { mu2 = c_mu[g + 8]; ni2 = c_nis[g + 8]; }

    float acc0 = 0.f, acc1 = 0.f, acc2 = 0.f;

    __shared__ alignas(16) float Ds[16][CH];
    __shared__ float msk[16];

    int ld_begin = chunk * chunkRows;
    for (int ld0 = ld_begin; ld0 < ld_begin + chunkRows; ld0 += 16) {
        __syncthreads();
        {
            #pragma unroll
            for (int i = t; i < 512; i += 256) {
                int r = i >> 5, c = i & 31;
                int row = ld0 + r;
                float4 v = make_float4(0.f, 0.f, 0.f, 0.f);
                if (row < Ld)
                    v = reinterpret_cast<const float4*>(D + ((size_t)b * Ld + row) * CH)[c];
                reinterpret_cast<float4*>(&Ds[r][0])[c] = v;
            }
            if (t < 16) {
                int rr = ld0 + t;
                msk[t] = (rr < Ld) ? md[(size_t)b * md_stride + rr] : 0.f;
            }
        }
        __syncthreads();
        #pragma unroll
        for (int r = 0; r < 16; r++) {
            const float4* dp = reinterpret_cast<const float4*>(&Ds[r][0]);
            float s = 0.f;
            #pragma unroll
            for (int i = 0; i < 8; i++) {
                float4 d4 = dp[g + 4 * i];
                float4 q4 = qreg[i];
                s += d4.x * q4.x + d4.y * q4.y + d4.z * q4.z + d4.w * q4.w;
            }
            s += __shfl_xor_sync(0xffffffffu, s, 1);
            s += __shfl_xor_sync(0xffffffffu, s, 2);
            float m = msk[r];
            float dd0 = s - mu0; acc0 += m * __expf(dd0 * dd0 * ni0);
            float dd1 = s - mu1; acc1 += m * __expf(dd1 * dd1 * ni1);
            if (has2) { float dd2 = s - mu2; acc2 += m * __expf(dd2 * dd2 * ni2); }
        }
    }

    size_t base = ((size_t)slot * BB + b) * (QR_TOT * NB) + (size_t)qr * NB;
    part[base + g]     = acc0;
    part[base + g + 4] = acc1;
    if (has2) part[base + g + 8] = acc2;
}

// ---------------- final: reduce chunk partials, log, mask, dense dot, tanh ----------------
__global__ void __launch_bounds__(256) final_kernel(
        const float* __restrict__ part, const float* __restrict__ qwm,
        const float* __restrict__ qem, const float* __restrict__ dW,
        const float* __restrict__ dB, float* __restrict__ out) {
    int b = blockIdx.x, t = threadIdx.x;
    float local = 0.f;
    for (int p = 0; p < NPAIR; p++) {
        int qsrc = c_pq[p], dmat = c_pd[p];
        int Lqp = c_qlen[qsrc], off = c_qoff[qsrc];
        int slot = c_dslot[dmat], nch = c_dnch[dmat];
        int tot = Lqp * NB;
        for (int idx = t; idx < tot; idx += 256) {
            int lq = idx / NB, k = idx - lq * NB;
            int row = off + lq;
            float s = 0.f;
            for (int c = 0; c < nch; c++)
                s += part[((size_t)(slot + c) * BB + b) * (QR_TOT * NB) + row * NB + k];
            float mq = (qsrc < 3) ? qwm[b * 20 + lq] : qem[b * 5 + lq];
            local += dW[p * NB + k] * (__logf(fmaxf(s, 1e-10f)) * 0.01f * mq);
        }
    }
    #pragma unroll
    for (int off = 16; off > 0; off >>= 1) local += __shfl_xor_sync(0xffffffffu, local, off);
    __shared__ float r8[8];
    if ((t & 31) == 0) r8[t >> 5] = local;
    __syncthreads();
    if (t == 0) {
        float s = 0.f;
        #pragma unroll
        for (int w = 0; w < 8; w++) s += r8[w];
        out[b] = tanhf(s + dB[0]);
    }
}

// ---------------- launcher ----------------
extern "C" void kernel_launch(void* const* d_in, const int* in_sizes, int n_in,
                              void* d_out, int out_size) {
    const int*   qwt = (const int*)d_in[0];
    const float* qwm = (const float*)d_in[1];
    const int*   qei = (const int*)d_in[2];
    const int*   qet = (const int*)d_in[3];
    const int*   qew = (const int*)d_in[4];
    const float* qem = (const float*)d_in[5];
    const int*   dwt = (const int*)d_in[6];
    const float* dwm = (const float*)d_in[7];
    const int*   dei = (const int*)d_in[8];
    const int*   det = (const int*)d_in[9];
    const int*   dew = (const int*)d_in[10];
    const float* dem = (const float*)d_in[11];
    const float* wrd = (const float*)d_in[12];
    const float* ent = (const float*)d_in[13];
    const float* car = (const float*)d_in[14];
    const float* bowW = (const float*)d_in[15];
    const float* bowB = (const float*)d_in[16];
    const float* cuW = (const float*)d_in[17];
    const float* cuB = (const float*)d_in[18];
    const float* cbW = (const float*)d_in[19];
    const float* cbB = (const float*)d_in[20];
    const float* ctW = (const float*)d_in[21];
    const float* ctB = (const float*)d_in[22];
    const float* cdW = (const float*)d_in[23];
    const float* cdB = (const float*)d_in[24];
    const float* dfW = (const float*)d_in[25];
    const float* dfB = (const float*)d_in[26];
    float* out = (float*)d_out;

    float* S = nullptr;
    cudaGetSymbolAddress((void**)&S, g_scratch);
    float* qw    = S + OFF_QW;
    float* dw    = S + OFF_DW;
    float* qbow  = S + OFF_QBOW;
    float* dbow  = S + OFF_DBOW;
    float* qu    = S + OFF_QU;
    float* qb    = S + OFF_QB;
    float* qt    = S + OFF_QT;
    float* du    = S + OFF_DU;
    float* db    = S + OFF_DB;
    float* dt    = S + OFF_DT;
    float* qs    = S + OFF_QS;
    float* ds    = S + OFF_DS;
    float* cs1   = S + OFF_CS1;
    float* cs8   = S + OFF_CS8;
    float* partP = S + OFF_PART;

    // #1, #2
    gather_kernel<<<(BB * LQ * 75 + 255) / 256, 256>>>(wrd, qwt, qw, BB * LQ);
    gather_kernel<<<(BB * LD * 75 + 255) / 256, 256>>>(wrd, dwt, dw, BB * LD);
    // #3
    colsum_kernel<<<dim3(NCD, BB), 128>>>(dw, LD, LD / NCD, cs8);
    // #4 — PROFILED by ncu: merged K=3 conv (doc 8 tiles + query 1 tile)
    wordconv4_kernel<3><<<dim3(9, BB), 256>>>(dw, LD, 510, qw, 18, ctW, ctB, dt, qt, 8);
    // #5..#7
    colsum_kernel<<<dim3(1, BB), 128>>>(qw, LQ, 20, cs1);
    bow2_kernel<<<BB, 128>>>(cs1, 1, LQ, bowW, bowB, qbow);
    bow2_kernel<<<BB, 128>>>(cs8, NCD, LD, bowW, bowB, dbow);
    // #8 — merged entity (q: blocks 0-4, d: blocks 5-14)
    entity2_kernel<<<dim3(EQ + ED, BB), 128>>>(qei, qet, qew, qbow, dei, det, dew, dbow,
                                               wrd, ent, car, cdW, cdB, qs, ds);
    // #9, #10 — merged K=1, K=2 convs
    wordconv4_kernel<1><<<dim3(9, BB), 256>>>(dw, LD, 512, qw, 20, cuW, cuB, du, qu, 8);
    wordconv4_kernel<2><<<dim3(9, BB), 256>>>(dw, LD, 511, qw, 19, cbW, cbB, db, qb, 8);
    // #11 — all pooling in one launch
    pool_all_kernel<<<dim3(PSLOTS, BB), 256>>>(qu, qb, qt, qs, du, db, dt, ds,
                                               dwm, dem, partP);
    // #12
    final_kernel<<<BB, 256>>>(partP, qwm, qem, dfW, dfB, out);
}

// round 5
// speedup vs baseline: 2.9761x; 1.0823x over previous
#include <cuda_runtime.h>
#include <cstdint>
#include <math.h>

// ---------------- problem constants ----------------
constexpr int BB = 64, LQ = 20, LD = 512, DIM = 300, NB = 11, WIN = 5;
constexpr int EQ = 5, ED = 10, DESC = 20, KC = 10;
constexpr int CH = 128;
constexpr int NPAIR = 16;
constexpr int QR_TOT = 64;     // 62 real q rows (20+19+18+5) padded to 64
constexpr int PSLOTS = 13;     // 4 chunks x 3 big D mats + 1 for ds
constexpr int NCD = 16;        // colsum chunks for doc

__constant__ float c_mu[NB]  = {1.0f, 0.9f, 0.7f, 0.5f, 0.3f, 0.1f, -0.1f, -0.3f, -0.5f, -0.7f, -0.9f};
// -0.5 / sigma^2
__constant__ float c_nis[NB] = {-500000.0f, -50.0f, -50.0f, -50.0f, -50.0f, -50.0f, -50.0f, -50.0f, -50.0f, -50.0f, -50.0f};

// pair -> (q source, d source) per reference pools order
__constant__ int c_pq[NPAIR]  = {0,0,0,1,2,1,1,2,2,3,3,3,0,1,2,3};
__constant__ int c_pd[NPAIR]  = {0,2,1,0,0,1,2,1,2,0,1,2,3,3,3,3};
__constant__ int c_qoff[4]    = {0,20,39,57};
__constant__ int c_qlen[4]    = {20,19,18,5};
__constant__ int c_dslot[4]   = {0,4,8,12};
__constant__ int c_dnch[4]    = {4,4,4,1};

// ---------------- scratch layout ----------------
constexpr size_t OFF_QW   = 0;                                   // B*LQ*300
constexpr size_t OFF_DW   = OFF_QW   + (size_t)BB*LQ*DIM;        // B*LD*300
constexpr size_t OFF_QBOW = OFF_DW   + (size_t)BB*LD*DIM;        // B*128
constexpr size_t OFF_DBOW = OFF_QBOW + (size_t)BB*CH;
constexpr size_t OFF_QU   = OFF_DBOW + (size_t)BB*CH;            // B*20*128
constexpr size_t OFF_QB   = OFF_QU   + (size_t)BB*20*CH;         // B*19*128
constexpr size_t OFF_QT   = OFF_QB   + (size_t)BB*19*CH;         // B*18*128
constexpr size_t OFF_DU   = OFF_QT   + (size_t)BB*18*CH;         // B*512*128
constexpr size_t OFF_DB   = OFF_DU   + (size_t)BB*512*CH;        // B*511*128
constexpr size_t OFF_DT   = OFF_DB   + (size_t)BB*511*CH;        // B*510*128
constexpr size_t OFF_QS   = OFF_DT   + (size_t)BB*510*CH;        // B*5*128
constexpr size_t OFF_DS   = OFF_QS   + (size_t)BB*EQ*CH;         // B*10*128
constexpr size_t OFF_CS1  = OFF_DS   + (size_t)BB*ED*CH;         // B*300     (q colsum)
constexpr size_t OFF_CS8  = OFF_CS1  + (size_t)BB*DIM;           // B*16*300  (d colsum)
constexpr size_t OFF_PART = OFF_CS8  + (size_t)BB*NCD*DIM;       // 13*B*64*11
constexpr size_t SCRATCH_TOTAL = OFF_PART + (size_t)PSLOTS*BB*QR_TOT*NB;

__device__ float g_scratch[SCRATCH_TOTAL];

// ---------------- gather: out[r,:] = emb[tok[r],:]  (300 floats = 75 float4) ----------------
__global__ void gather_kernel(const float* __restrict__ emb, const int* __restrict__ tok,
                              float* __restrict__ out, int nrows) {
    int idx = blockIdx.x * blockDim.x + threadIdx.x;
    int total = nrows * 75;
    if (idx >= total) return;
    int r = idx / 75, c = idx - r * 75;
    reinterpret_cast<float4*>(out)[idx] =
        reinterpret_cast<const float4*>(emb)[(size_t)tok[r] * 75 + c];
}

// ---------------- column-sum partials: out[b,c,d] = sum over rows chunk c ----------------
__global__ void colsum_kernel(const float* __restrict__ X, int L, int rows,
                              float* __restrict__ outp) {
    int c = blockIdx.x, b = blockIdx.y;
    int NC = gridDim.x;
    int t = threadIdx.x;
    int r0 = c * rows;
    for (int d = t; d < DIM; d += blockDim.x) {
        float s = 0.f;
        #pragma unroll 4
        for (int r = 0; r < rows; r++) {
            int row = r0 + r;
            if (row < L) s += X[((size_t)b * L + row) * DIM + d];
        }
        outp[((size_t)b * NC + c) * DIM + d] = s;
    }
}

// ---------------- bow stage2: reduce partials + matvec with bow_W ----------------
__global__ void bow2_kernel(const float* __restrict__ partS, int NC, int L,
                            const float* __restrict__ W, const float* __restrict__ bias,
                            float* __restrict__ out) {
    int b = blockIdx.x, o = threadIdx.x;   // 128 threads
    __shared__ float ssum[DIM];
    for (int d = o; d < DIM; d += CH) {
        float s = 0.f;
        for (int c = 0; c < NC; c++) s += partS[((size_t)b * NC + c) * DIM + d];
        ssum[d] = s;
    }
    __syncthreads();
    float acc = 0.f;
    const float* wr = W + (size_t)o * DIM;
    #pragma unroll 4
    for (int d = 0; d < DIM; d++) acc += ssum[d] * wr[d];
    out[b * CH + o] = acc + (float)L * bias[o];
}

// ---------------- conv body (templated K), identical math to round-4 ----------------
template <int K>
__device__ __forceinline__ void conv_body(
        const float* __restrict__ X, int L, int Lout,
        const float* __restrict__ W, const float* __restrict__ bias,
        float* __restrict__ out, int n, int l0,
        float* Ws, float* Xs) {
    constexpr int DC = 20;
    constexpr int WST = (K == 1) ? 20 : (K == 2) ? 44 : 68;
    constexpr int LT = 64;
    constexpr int XR = LT + K - 1;

    int t = threadIdx.x;
    int cg = t & 31, pg = t >> 5;

    float acc[4][8];
    #pragma unroll
    for (int u = 0; u < 4; u++)
        #pragma unroll
        for (int r = 0; r < 8; r++) acc[u][r] = 0.f;

    for (int d0 = 0; d0 < DIM; d0 += DC) {
        __syncthreads();
        for (int i = t; i < CH * K * 5; i += 256) {
            int ch = i / (K * 5), rem = i - ch * (K * 5);
            int tap = rem / 5, q = rem - tap * 5;
            *reinterpret_cast<float4*>(&Ws[ch * WST + tap * DC + q * 4]) =
                *reinterpret_cast<const float4*>(&W[(size_t)ch * K * DIM + (size_t)tap * DIM + d0 + q * 4]);
        }
        for (int i = t; i < XR * 5; i += 256) {
            int r = i / 5, q = i - r * 5;
            int lg = l0 + r;
            float4 v = make_float4(0.f, 0.f, 0.f, 0.f);
            if (lg < L)
                v = *reinterpret_cast<const float4*>(&X[((size_t)n * L + lg) * DIM + d0 + q * 4]);
            *reinterpret_cast<float4*>(&Xs[r * DC + q * 4]) = v;
        }
        __syncthreads();
        #pragma unroll
        for (int jq = 0; jq < DC / 4; jq++) {
            float4 xr[8 + K - 1];
            #pragma unroll
            for (int r = 0; r < 8 + K - 1; r++)
                xr[r] = *reinterpret_cast<const float4*>(&Xs[(pg * 8 + r) * DC + jq * 4]);
            #pragma unroll
            for (int u = 0; u < 4; u++) {
                #pragma unroll
                for (int tap = 0; tap < K; tap++) {
                    float4 w4 = *reinterpret_cast<const float4*>(
                        &Ws[(cg + 32 * u) * WST + tap * DC + jq * 4]);
                    #pragma unroll
                    for (int r = 0; r < 8; r++) {
                        float a = acc[u][r];
                        a = fmaf(w4.x, xr[r + tap].x, a);
                        a = fmaf(w4.y, xr[r + tap].y, a);
                        a = fmaf(w4.z, xr[r + tap].z, a);
                        a = fmaf(w4.w, xr[r + tap].w, a);
                        acc[u][r] = a;
                    }
                }
            }
        }
    }

    float bvals[4];
    #pragma unroll
    for (int u = 0; u < 4; u++) bvals[u] = bias[cg + 32 * u];

    #pragma unroll
    for (int r = 0; r < 8; r++) {
        int p = pg * 8 + r;
        float v[4];
        float ss = 0.f;
        #pragma unroll
        for (int u = 0; u < 4; u++) {
            v[u] = fmaxf(acc[u][r] + bvals[u], 0.f);
            ss += v[u] * v[u];
        }
        #pragma unroll
        for (int off = 16; off > 0; off >>= 1) ss += __shfl_xor_sync(0xffffffffu, ss, off);
        float inv = 1.f / fmaxf(sqrtf(ss), 1e-10f);
        if (l0 + p < Lout) {
            float* op = out + ((size_t)n * Lout + l0 + p) * CH;
            #pragma unroll
            for (int u = 0; u < 4; u++) op[cg + 32 * u] = v[u] * inv;
        }
    }
}

// ---------------- all three word convs (doc + query) in ONE launch ----------------
// gridDim.x = 27: [0,9)->K=3, [9,18)->K=1, [18,27)->K=2. tile 8 within each = query.
__global__ void __launch_bounds__(256) allconv_kernel(
        const float* __restrict__ dw, const float* __restrict__ qw,
        const float* __restrict__ cuW, const float* __restrict__ cuB,
        const float* __restrict__ cbW, const float* __restrict__ cbB,
        const float* __restrict__ ctW, const float* __restrict__ ctB,
        float* __restrict__ du, float* __restrict__ qu,
        float* __restrict__ db, float* __restrict__ qb,
        float* __restrict__ dt, float* __restrict__ qt) {
    __shared__ alignas(16) float Ws[CH * 68];
    __shared__ alignas(16) float Xs[66 * 20];
    int gx = blockIdx.x, n = blockIdx.y;
    int grp = gx / 9, tile = gx - grp * 9;
    bool isQ = (tile == 8);
    const float* X = isQ ? qw : dw;
    int L = isQ ? LQ : LD;
    int l0 = isQ ? 0 : tile * 64;
    if (grp == 0) {
        conv_body<3>(X, L, isQ ? 18 : 510, ctW, ctB, isQ ? qt : dt, n, l0, Ws, Xs);
    } else if (grp == 1) {
        conv_body<1>(X, L, isQ ? 20 : 512, cuW, cuB, isQ ? qu : du, n, l0, Ws, Xs);
    } else {
        conv_body<2>(X, L, isQ ? 19 : 511, cbW, cbB, isQ ? qb : db, n, l0, Ws, Xs);
    }
}

// ---------------- entity branch merged q+d: desc conv(max) + attention + L2 ----------------
__global__ void __launch_bounds__(128) entity2_kernel(
        const int* __restrict__ qei, const int* __restrict__ qet, const int* __restrict__ qew,
        const float* __restrict__ qbow,
        const int* __restrict__ dei, const int* __restrict__ det, const int* __restrict__ dew,
        const float* __restrict__ dbow,
        const float* __restrict__ wrd_emb, const float* __restrict__ ent_emb,
        const float* __restrict__ car_emb,
        const float* __restrict__ W, const float* __restrict__ bias,
        float* __restrict__ qs_out, float* __restrict__ ds_out) {
    constexpr int K = WIN, DC = 12, LT = 16, WST = 60;
    __shared__ alignas(16) float Ws[CH * WST];
    __shared__ alignas(16) float Xs[DESC * DC];
    __shared__ int toks[DESC];
    __shared__ int crows[KC];
    __shared__ float bv[CH];
    __shared__ float logits[KC];
    __shared__ float att[KC];
    __shared__ float red[4];

    int eg = blockIdx.x, b = blockIdx.y;
    bool isQ = (eg < EQ);
    int e = isQ ? eg : eg - EQ;
    int n_ent = isQ ? EQ : ED;
    const int* ids_e   = isQ ? qei : dei;
    const int* ids_desc= isQ ? qet : det;
    const int* ids_car = isQ ? qew : dew;
    const float* bow   = isQ ? qbow : dbow;
    float* out         = isQ ? qs_out : ds_out;

    int o = threadIdx.x;
    int warp = o >> 5, lane = o & 31;

    if (o < DESC) toks[o] = ids_desc[(size_t)b * n_ent * DESC + e * DESC + o];
    if (o < KC)   crows[o] = ids_car[(size_t)b * n_ent * KC + e * KC + o];
    bv[o] = bow[b * CH + o];
    __syncthreads();

    float acc[LT];
    #pragma unroll
    for (int p = 0; p < LT; p++) acc[p] = 0.f;

    for (int d0 = 0; d0 < DIM; d0 += DC) {
        for (int i = o; i < CH * K * 3; i += CH) {
            int ch = i / (K * 3), rem = i - ch * (K * 3);
            int tap = rem / 3, q = rem - tap * 3;
            *reinterpret_cast<float4*>(&Ws[ch * WST + tap * DC + q * 4]) =
                *reinterpret_cast<const float4*>(&W[(size_t)ch * K * DIM + (size_t)tap * DIM + d0 + q * 4]);
        }
        for (int i = o; i < DESC * 3; i += CH) {
            int r = i / 3, q = i - r * 3;
            *reinterpret_cast<float4*>(&Xs[r * DC + q * 4]) =
                *reinterpret_cast<const float4*>(&wrd_emb[(size_t)toks[r] * DIM + d0 + q * 4]);
        }
        __syncthreads();
        #pragma unroll
        for (int jq = 0; jq < DC / 4; jq++) {
            float4 xr[DESC];
            #pragma unroll
            for (int r = 0; r < DESC; r++)
                xr[r] = *reinterpret_cast<const float4*>(&Xs[r * DC + jq * 4]);
            #pragma unroll
            for (int tap = 0; tap < K; tap++) {
                float4 w4 = *reinterpret_cast<const float4*>(&Ws[o * WST + tap * DC + jq * 4]);
                #pragma unroll
                for (int p = 0; p < LT; p++) {
                    float a = acc[p];
                    a = fmaf(w4.x, xr[p + tap].x, a);
                    a = fmaf(w4.y, xr[p + tap].y, a);
                    a = fmaf(w4.z, xr[p + tap].z, a);
                    a = fmaf(w4.w, xr[p + tap].w, a);
                    acc[p] = a;
                }
            }
        }
        __syncthreads();
    }
    float bo = bias[o];
    float econv = 0.f;
    #pragma unroll
    for (int p = 0; p < LT; p++) econv = fmaxf(econv, fmaxf(acc[p] + bo, 0.f));

    if (o < KC) {
        const float* cr = car_emb + (size_t)crows[o] * CH;
        float s = 0.f;
        #pragma unroll 4
        for (int c = 0; c < CH; c++) s += bv[c] * cr[c];
        logits[o] = s;
    }
    __syncthreads();
    if (o == 0) {
        float mx = -1e30f;
        #pragma unroll
        for (int k = 0; k < KC; k++) mx = fmaxf(mx, logits[k]);
        float ssum = 0.f;
        #pragma unroll
        for (int k = 0; k < KC; k++) { float ev = __expf(logits[k] - mx); att[k] = ev; ssum += ev; }
        float inv = 1.f / ssum;
        #pragma unroll
        for (int k = 0; k < KC; k++) att[k] *= inv;
    }
    __syncthreads();
    float ew = 0.f;
    #pragma unroll
    for (int k = 0; k < KC; k++) ew += att[k] * car_emb[(size_t)crows[k] * CH + o];

    float v = ent_emb[(size_t)ids_e[b * n_ent + e] * CH + o] + econv + ew;

    float ss = v * v;
    #pragma unroll
    for (int off = 16; off > 0; off >>= 1) ss += __shfl_xor_sync(0xffffffffu, ss, off);
    if (lane == 0) red[warp] = ss;
    __syncthreads();
    float tot = red[0] + red[1] + red[2] + red[3];
    float inv = 1.f / fmaxf(sqrtf(tot), 1e-10f);
    out[((size_t)b * n_ent + e) * CH + o] = v * inv;
}

// ---------------- fused kernel pooling (single launch): slot = blockIdx.x in [0,13) ----------------
__global__ void __launch_bounds__(256) pool_all_kernel(
        const float* __restrict__ Qu, const float* __restrict__ Qb,
        const float* __restrict__ Qt, const float* __restrict__ Qs,
        const float* __restrict__ Du, const float* __restrict__ Db,
        const float* __restrict__ Dt, const float* __restrict__ Dsm,
        const float* __restrict__ dwm, const float* __restrict__ dem,
        float* __restrict__ part) {
    int slot = blockIdx.x, b = blockIdx.y;
    int dm = slot >> 2;
    int chunk = slot & 3;
    const float* D  = (dm == 0) ? Du : (dm == 1) ? Db : (dm == 2) ? Dt : Dsm;
    int Ld          = (dm == 0) ? 512 : (dm == 1) ? 511 : (dm == 2) ? 510 : 10;
    const float* md = (dm < 3) ? dwm : dem;
    int md_stride   = (dm < 3) ? 512 : 10;
    int chunkRows   = (dm < 3) ? 128 : 16;

    int t = threadIdx.x;
    int qr = t >> 2, g = t & 3;

    float4 qreg[8];
    const float* qptr = nullptr;
    if (qr < 20)      qptr = Qu + (size_t)(b * 20 + qr) * CH;
    else if (qr < 39) qptr = Qb + (size_t)(b * 19 + (qr - 20)) * CH;
    else if (qr < 57) qptr = Qt + (size_t)(b * 18 + (qr - 39)) * CH;
    else if (qr < 62) qptr = Qs + (size_t)(b * 5 + (qr - 57)) * CH;
    if (qptr) {
        const float4* q4 = reinterpret_cast<const float4*>(qptr);
        #pragma unroll
        for (int i = 0; i < 8; i++) qreg[i] = q4[g + 4 * i];
    } else {
        #pragma unroll
        for (int i = 0; i < 8; i++) qreg[i] = make_float4(0.f, 0.f, 0.f, 0.f);
    }

    float mu0 = c_mu[g],     ni0 = c_nis[g];
    float mu1 = c_mu[g + 4], ni1 = c_nis[g + 4];
    float mu2 = 0.f, ni2 = 0.f;
    bool has2 = (g + 8) < NB;
    if (has2) { mu2 = c_mu[g + 8]; ni2 = c_nis[g + 8]; }

    float acc0 = 0.f, acc1 = 0.f, acc2 = 0.f;

    __shared__ alignas(16) float Ds[16][CH];
    __shared__ float msk[16];

    int ld_begin = chunk * chunkRows;
    for (int ld0 = ld_begin; ld0 < ld_begin + chunkRows; ld0 += 16) {
        __syncthreads();
        {
            #pragma unroll
            for (int i = t; i < 512; i += 256) {
                int r = i >> 5, c = i & 31;
                int row = ld0 + r;
                float4 v = make_float4(0.f, 0.f, 0.f, 0.f);
                if (row < Ld)
                    v = reinterpret_cast<const float4*>(D + ((size_t)b * Ld + row) * CH)[c];
                reinterpret_cast<float4*>(&Ds[r][0])[c] = v;
            }
            if (t < 16) {
                int rr = ld0 + t;
                msk[t] = (rr < Ld) ? md[(size_t)b * md_stride + rr] : 0.f;
            }
        }
        __syncthreads();
        #pragma unroll
        for (int r = 0; r < 16; r++) {
            const float4* dp = reinterpret_cast<const float4*>(&Ds[r][0]);
            float s = 0.f;
            #pragma unroll
            for (int i = 0; i < 8; i++) {
                float4 d4 = dp[g + 4 * i];
                float4 q4 = qreg[i];
                s += d4.x * q4.x + d4.y * q4.y + d4.z * q4.z + d4.w * q4.w;
            }
            s += __shfl_xor_sync(0xffffffffu, s, 1);
            s += __shfl_xor_sync(0xffffffffu, s, 2);
            float m = msk[r];
            float a0 = (s - mu0) * (s - mu0) * ni0;
            float a1 = (s - mu1) * (s - mu1) * ni1;
            if (a0 > -60.f) acc0 += m * __expf(a0);
            if (a1 > -60.f) acc1 += m * __expf(a1);
            if (has2) {
                float a2 = (s - mu2) * (s - mu2) * ni2;
                if (a2 > -60.f) acc2 += m * __expf(a2);
            }
        }
    }

    size_t base = ((size_t)slot * BB + b) * (QR_TOT * NB) + (size_t)qr * NB;
    part[base + g]     = acc0;
    part[base + g + 4] = acc1;
    if (has2) part[base + g + 8] = acc2;
}

// ---------------- final: reduce chunk partials, log, mask, dense dot, tanh ----------------
__global__ void __launch_bounds__(256) final_kernel(
        const float* __restrict__ part, const float* __restrict__ qwm,
        const float* __restrict__ qem, const float* __restrict__ dW,
        const float* __restrict__ dB, float* __restrict__ out) {
    int b = blockIdx.x, t = threadIdx.x;
    float local = 0.f;
    for (int p = 0; p < NPAIR; p++) {
        int qsrc = c_pq[p], dmat = c_pd[p];
        int Lqp = c_qlen[qsrc], off = c_qoff[qsrc];
        int slot = c_dslot[dmat], nch = c_dnch[dmat];
        int tot = Lqp * NB;
        for (int idx = t; idx < tot; idx += 256) {
            int lq = idx / NB, k = idx - lq * NB;
            int row = off + lq;
            float s = 0.f;
            for (int c = 0; c < nch; c++)
                s += part[((size_t)(slot + c) * BB + b) * (QR_TOT * NB) + row * NB + k];
            float mq = (qsrc < 3) ? qwm[b * 20 + lq] : qem[b * 5 + lq];
            local += dW[p * NB + k] * (__logf(fmaxf(s, 1e-10f)) * 0.01f * mq);
        }
    }
    #pragma unroll
    for (int off = 16; off > 0; off >>= 1) local += __shfl_xor_sync(0xffffffffu, local, off);
    __shared__ float r8[8];
    if ((t & 31) == 0) r8[t >> 5] = local;
    __syncthreads();
    if (t == 0) {
        float s = 0.f;
        #pragma unroll
        for (int w = 0; w < 8; w++) s += r8[w];
        out[b] = tanhf(s + dB[0]);
    }
}

// ---------------- launcher ----------------
extern "C" void kernel_launch(void* const* d_in, const int* in_sizes, int n_in,
                              void* d_out, int out_size) {
    const int*   qwt = (const int*)d_in[0];
    const float* qwm = (const float*)d_in[1];
    const int*   qei = (const int*)d_in[2];
    const int*   qet = (const int*)d_in[3];
    const int*   qew = (const int*)d_in[4];
    const float* qem = (const float*)d_in[5];
    const int*   dwt = (const int*)d_in[6];
    const float* dwm = (const float*)d_in[7];
    const int*   dei = (const int*)d_in[8];
    const int*   det = (const int*)d_in[9];
    const int*   dew = (const int*)d_in[10];
    const float* dem = (const float*)d_in[11];
    const float* wrd = (const float*)d_in[12];
    const float* ent = (const float*)d_in[13];
    const float* car = (const float*)d_in[14];
    const float* bowW = (const float*)d_in[15];
    const float* bowB = (const float*)d_in[16];
    const float* cuW = (const float*)d_in[17];
    const float* cuB = (const float*)d_in[18];
    const float* cbW = (const float*)d_in[19];
    const float* cbB = (const float*)d_in[20];
    const float* ctW = (const float*)d_in[21];
    const float* ctB = (const float*)d_in[22];
    const float* cdW = (const float*)d_in[23];
    const float* cdB = (const float*)d_in[24];
    const float* dfW = (const float*)d_in[25];
    const float* dfB = (const float*)d_in[26];
    float* out = (float*)d_out;

    float* S = nullptr;
    cudaGetSymbolAddress((void**)&S, g_scratch);
    float* qw    = S + OFF_QW;
    float* dw    = S + OFF_DW;
    float* qbow  = S + OFF_QBOW;
    float* dbow  = S + OFF_DBOW;
    float* qu    = S + OFF_QU;
    float* qb    = S + OFF_QB;
    float* qt    = S + OFF_QT;
    float* du    = S + OFF_DU;
    float* db    = S + OFF_DB;
    float* dt    = S + OFF_DT;
    float* qs    = S + OFF_QS;
    float* ds    = S + OFF_DS;
    float* cs1   = S + OFF_CS1;
    float* cs8   = S + OFF_CS8;
    float* partP = S + OFF_PART;

    // one-time stream/event setup (no device memory involved)
    static cudaStream_t sSide = nullptr;
    static cudaEvent_t evG = nullptr, evE = nullptr;
    if (sSide == nullptr) {
        cudaStreamCreateWithFlags(&sSide, cudaStreamNonBlocking);
        cudaEventCreateWithFlags(&evG, cudaEventDisableTiming);
        cudaEventCreateWithFlags(&evE, cudaEventDisableTiming);
    }

    // #1, #2 — gathers on main stream
    gather_kernel<<<(BB * LQ * 75 + 255) / 256, 256>>>(wrd, qwt, qw, BB * LQ);
    gather_kernel<<<(BB * LD * 75 + 255) / 256, 256>>>(wrd, dwt, dw, BB * LD);
    cudaEventRecord(evG, 0);
    cudaStreamWaitEvent(sSide, evG, 0);

    // #3 — side chain starts (colsum doc)
    colsum_kernel<<<dim3(NCD, BB), 128, 0, sSide>>>(dw, LD, LD / NCD, cs8);
    // #4 — PROFILED: all word convs in one launch (main stream, concurrent with side)
    allconv_kernel<<<dim3(27, BB), 256>>>(dw, qw, cuW, cuB, cbW, cbB, ctW, ctB,
                                          du, qu, db, qb, dt, qt);
    // side chain continues: colsum q, bows, entity
    colsum_kernel<<<dim3(1, BB), 128, 0, sSide>>>(qw, LQ, 20, cs1);
    bow2_kernel<<<BB, 128, 0, sSide>>>(cs1, 1, LQ, bowW, bowB, qbow);
    bow2_kernel<<<BB, 128, 0, sSide>>>(cs8, NCD, LD, bowW, bowB, dbow);
    entity2_kernel<<<dim3(EQ + ED, BB), 128, 0, sSide>>>(qei, qet, qew, qbow,
                                                         dei, det, dew, dbow,
                                                         wrd, ent, car, cdW, cdB, qs, ds);
    cudaEventRecord(evE, sSide);
    cudaStreamWaitEvent(0, evE, 0);

    // pooling + final on main stream (after convs in-order, entity via event)
    pool_all_kernel<<<dim3(PSLOTS, BB), 256>>>(qu, qb, qt, qs, du, db, dt, ds,
                                               dwm, dem, partP);
    final_kernel<<<BB, 256>>>(partP, qwm, qem, dfW, dfB, out);
}